// round 3
// baseline (speedup 1.0000x reference)
#include <cuda_runtime.h>
#include <cstdint>
#include <math.h>

#define BB 2048
#define TT 128
#define SS 64
#define AA 32
#define G3 192
#define HH 128
#define OO 256

#define DEV __device__ __forceinline__

DEV void split_tf32(float x, uint32_t& hi, uint32_t& lo) {
    asm("cvt.rna.tf32.f32 %0, %1;" : "=r"(hi) : "f"(x));
    float l = x - __uint_as_float(hi);
    asm("cvt.rna.tf32.f32 %0, %1;" : "=r"(lo) : "f"(l));
}

DEV void mma_tf32(float* d, const uint32_t* a, uint32_t b0, uint32_t b1) {
    asm volatile(
        "mma.sync.aligned.m16n8k8.row.col.f32.tf32.tf32.f32 "
        "{%0,%1,%2,%3}, {%4,%5,%6,%7}, {%8,%9}, {%0,%1,%2,%3};"
        : "+f"(d[0]), "+f"(d[1]), "+f"(d[2]), "+f"(d[3])
        : "r"(a[0]), "r"(a[1]), "r"(a[2]), "r"(a[3]), "r"(b0), "r"(b1));
}

// ---------------------------------------------------------------------------
// Kernel 1: GRU scan (fp32). 128 CTAs x 16 rows, 256 threads.
// ---------------------------------------------------------------------------
struct ScanSmem {
    float Wt_ih[96][G3];
    float Wt_hh[64][G3];
    float bi[G3];
    float bh[G3];
    float h[16][SS];
    float a[16][AA];
    float gi[16][G3];
    float gh[16][G3];
};

__global__ void __launch_bounds__(256, 1)
scan_kernel(const float* __restrict__ initial_state,
            const float* __restrict__ actions,
            const float* __restrict__ W_ih,
            const float* __restrict__ W_hh,
            const float* __restrict__ b_ih,
            const float* __restrict__ b_hh,
            float* __restrict__ states) {
    extern __shared__ char smem_raw[];
    ScanSmem& sm = *reinterpret_cast<ScanSmem*>(smem_raw);
    const int tid = threadIdx.x;
    const int b0 = blockIdx.x * 16;

    for (int i = tid; i < G3 * 96; i += 256)
        sm.Wt_ih[i % 96][i / 96] = W_ih[i];
    for (int i = tid; i < G3 * 64; i += 256)
        sm.Wt_hh[i % 64][i / 64] = W_hh[i];
    for (int i = tid; i < G3; i += 256) { sm.bi[i] = b_ih[i]; sm.bh[i] = b_hh[i]; }
    for (int i = tid; i < 16 * SS; i += 256) {
        int r = i / SS, k = i % SS;
        float v = initial_state[(long)(b0 + r) * SS + k];
        sm.h[r][k] = v;
        states[(long)(b0 + r) * ((TT + 1) * SS) + k] = v;
    }
    __syncthreads();

    const int og = tid & 31;
    const int rp = tid >> 5;
    const int r0 = rp * 2, r1 = r0 + 1;
    const int g_row = tid >> 4;
    const int g_j = (tid & 15) * 4;

    for (int t = 0; t < TT; ++t) {
        {
            int r = tid >> 4, c = (tid & 15) * 2;
            const float2 av = *reinterpret_cast<const float2*>(
                &actions[((long)(b0 + r) * TT + t) * AA + c]);
            sm.a[r][c] = av.x; sm.a[r][c + 1] = av.y;
        }
        __syncthreads();

        float acc_i[6][2], acc_h[6][2];
        #pragma unroll
        for (int j = 0; j < 6; ++j) {
            acc_i[j][0] = acc_i[j][1] = 0.f;
            acc_h[j][0] = acc_h[j][1] = 0.f;
        }
        #pragma unroll 4
        for (int k = 0; k < 64; ++k) {
            const float x0 = sm.h[r0][k], x1 = sm.h[r1][k];
            const float* wi = &sm.Wt_ih[k][og];
            const float* wh = &sm.Wt_hh[k][og];
            #pragma unroll
            for (int j = 0; j < 6; ++j) {
                const float wiv = wi[32 * j], whv = wh[32 * j];
                acc_i[j][0] = fmaf(wiv, x0, acc_i[j][0]);
                acc_i[j][1] = fmaf(wiv, x1, acc_i[j][1]);
                acc_h[j][0] = fmaf(whv, x0, acc_h[j][0]);
                acc_h[j][1] = fmaf(whv, x1, acc_h[j][1]);
            }
        }
        #pragma unroll 4
        for (int k = 0; k < 32; ++k) {
            const float x0 = sm.a[r0][k], x1 = sm.a[r1][k];
            const float* wi = &sm.Wt_ih[64 + k][og];
            #pragma unroll
            for (int j = 0; j < 6; ++j) {
                const float wiv = wi[32 * j];
                acc_i[j][0] = fmaf(wiv, x0, acc_i[j][0]);
                acc_i[j][1] = fmaf(wiv, x1, acc_i[j][1]);
            }
        }
        #pragma unroll
        for (int j = 0; j < 6; ++j) {
            const int o = og + 32 * j;
            sm.gi[r0][o] = acc_i[j][0]; sm.gi[r1][o] = acc_i[j][1];
            sm.gh[r0][o] = acc_h[j][0]; sm.gh[r1][o] = acc_h[j][1];
        }
        __syncthreads();

        float hq[4];
        #pragma unroll
        for (int u = 0; u < 4; ++u) {
            const int j = g_j + u;
            const float sr = sm.gi[g_row][j] + sm.bi[j] + sm.gh[g_row][j] + sm.bh[j];
            const float sz = sm.gi[g_row][64 + j] + sm.bi[64 + j]
                           + sm.gh[g_row][64 + j] + sm.bh[64 + j];
            const float gni = sm.gi[g_row][128 + j] + sm.bi[128 + j];
            const float gnh = sm.gh[g_row][128 + j] + sm.bh[128 + j];
            const float rg = 1.0f / (1.0f + expf(-sr));
            const float zg = 1.0f / (1.0f + expf(-sz));
            const float ng = tanhf(gni + rg * gnh);
            hq[u] = (1.0f - zg) * ng + zg * sm.h[g_row][j];
        }
        #pragma unroll
        for (int u = 0; u < 4; ++u) sm.h[g_row][g_j + u] = hq[u];
        *reinterpret_cast<float4*>(
            &states[((long)(b0 + g_row) * (TT + 1) + t + 1) * SS + g_j]) =
            make_float4(hq[0], hq[1], hq[2], hq[3]);
        __syncthreads();
    }
}

// ---------------------------------------------------------------------------
// Kernel 2: heads, tf32x3 mma. 2048 CTAs x 128 rows, 512 threads (16 warps).
// ---------------------------------------------------------------------------
#define LDX 68
#define LDA1 132
#define LDW1 264
#define LDW2 136

struct HeadSmem {
    float X[128][LDX];
    float A1[128][LDA1];
    float Wbuf[128 * LDW2];  // L1 uses [64][LDW1], L2 uses [128][LDW2]
    float b1s[256];
    float b2s[256];
    float w2r[64];
    float w2s[64];
};

__global__ void __launch_bounds__(512, 1)
heads_kernel(const float* __restrict__ states,
             const float* __restrict__ dec_w1, const float* __restrict__ dec_b1,
             const float* __restrict__ dec_w2, const float* __restrict__ dec_b2,
             const float* __restrict__ rew_w1, const float* __restrict__ rew_b1,
             const float* __restrict__ rew_w2, const float* __restrict__ rew_b2,
             const float* __restrict__ saf_w1, const float* __restrict__ saf_b1,
             const float* __restrict__ saf_w2, const float* __restrict__ saf_b2,
             float* __restrict__ obs, float* __restrict__ rew,
             float* __restrict__ saf) {
    extern __shared__ char smem_raw[];
    HeadSmem& sm = *reinterpret_cast<HeadSmem*>(smem_raw);
    const int tid = threadIdx.x;
    const int m0 = blockIdx.x * 128;

    for (int i = tid; i < 128 * 16; i += 512) {
        const int r = i >> 4, c4 = (i & 15) * 4;
        const int m = m0 + r, b = m >> 7, t = m & 127;
        *reinterpret_cast<float4*>(&sm.X[r][c4]) =
            *reinterpret_cast<const float4*>(&states[((long)b * (TT + 1) + t + 1) * SS + c4]);
    }
    for (int i = tid; i < 256 * 64; i += 512) {
        const int n = i >> 6, k = i & 63;
        float w;
        if (n < 128)      w = dec_w1[n * 64 + k];
        else if (n < 192) w = rew_w1[(n - 128) * 64 + k];
        else              w = saf_w1[(n - 192) * 64 + k];
        sm.Wbuf[k * LDW1 + n] = w;
    }
    for (int i = tid; i < 256; i += 512) {
        sm.b1s[i] = (i < 128) ? dec_b1[i] : ((i < 192) ? rew_b1[i - 128] : saf_b1[i - 192]);
        sm.b2s[i] = dec_b2[i];
    }
    for (int i = tid; i < 64; i += 512) { sm.w2r[i] = rew_w2[i]; sm.w2s[i] = saf_w2[i]; }
    __syncthreads();

    const int lane = tid & 31;
    const int w = tid >> 5;
    const int wr = w & 3;
    const int wc = w >> 2;
    const int gid = lane >> 2;
    const int t4 = lane & 3;

    // ---- Layer 1: (128x64) @ (64x256) ----
    float acc[2][8][4];
    #pragma unroll
    for (int mt = 0; mt < 2; ++mt)
        #pragma unroll
        for (int nt = 0; nt < 8; ++nt)
            #pragma unroll
            for (int q = 0; q < 4; ++q) acc[mt][nt][q] = 0.f;

    #pragma unroll
    for (int ks = 0; ks < 8; ++ks) {
        const int k0 = ks * 8;
        uint32_t ah[2][4], al[2][4];
        #pragma unroll
        for (int mt = 0; mt < 2; ++mt) {
            const int R = wr * 32 + mt * 16;
            split_tf32(sm.X[R + gid][k0 + t4],         ah[mt][0], al[mt][0]);
            split_tf32(sm.X[R + gid + 8][k0 + t4],     ah[mt][1], al[mt][1]);
            split_tf32(sm.X[R + gid][k0 + t4 + 4],     ah[mt][2], al[mt][2]);
            split_tf32(sm.X[R + gid + 8][k0 + t4 + 4], ah[mt][3], al[mt][3]);
        }
        #pragma unroll
        for (int nt = 0; nt < 8; ++nt) {
            const int n0 = wc * 64 + nt * 8;
            uint32_t bh0, bl0, bh1, bl1;
            split_tf32(sm.Wbuf[(k0 + t4) * LDW1 + n0 + gid], bh0, bl0);
            split_tf32(sm.Wbuf[(k0 + t4 + 4) * LDW1 + n0 + gid], bh1, bl1);
            #pragma unroll
            for (int mt = 0; mt < 2; ++mt) {
                mma_tf32(acc[mt][nt], ah[mt], bh0, bh1);
                mma_tf32(acc[mt][nt], al[mt], bh0, bh1);
                mma_tf32(acc[mt][nt], ah[mt], bl0, bl1);
            }
        }
    }

    if (wc < 2) {
        #pragma unroll
        for (int mt = 0; mt < 2; ++mt) {
            const int R = wr * 32 + mt * 16;
            #pragma unroll
            for (int nt = 0; nt < 8; ++nt) {
                const int col = wc * 64 + nt * 8 + t4 * 2;
                const float bA = sm.b1s[col], bBv = sm.b1s[col + 1];
                sm.A1[R + gid][col]         = fmaxf(acc[mt][nt][0] + bA, 0.f);
                sm.A1[R + gid][col + 1]     = fmaxf(acc[mt][nt][1] + bBv, 0.f);
                sm.A1[R + gid + 8][col]     = fmaxf(acc[mt][nt][2] + bA, 0.f);
                sm.A1[R + gid + 8][col + 1] = fmaxf(acc[mt][nt][3] + bBv, 0.f);
            }
        }
    } else {
        const bool is_rew = (wc == 2);
        const float* w2v = is_rew ? sm.w2r : sm.w2s;
        const int bbase = is_rew ? 128 : 192;
        const float bias2 = is_rew ? rew_b2[0] : saf_b2[0];
        float* outp = is_rew ? rew : saf;
        #pragma unroll
        for (int mt = 0; mt < 2; ++mt) {
            float p0 = 0.f, p1 = 0.f;
            #pragma unroll
            for (int nt = 0; nt < 8; ++nt) {
                const int l = nt * 8 + t4 * 2;
                const float bA = sm.b1s[bbase + l], bBv = sm.b1s[bbase + l + 1];
                const float v00 = fmaxf(acc[mt][nt][0] + bA, 0.f);
                const float v01 = fmaxf(acc[mt][nt][1] + bBv, 0.f);
                const float v10 = fmaxf(acc[mt][nt][2] + bA, 0.f);
                const float v11 = fmaxf(acc[mt][nt][3] + bBv, 0.f);
                p0 = fmaf(v00, w2v[l], fmaf(v01, w2v[l + 1], p0));
                p1 = fmaf(v10, w2v[l], fmaf(v11, w2v[l + 1], p1));
            }
            p0 += __shfl_xor_sync(0xFFFFFFFFu, p0, 1);
            p0 += __shfl_xor_sync(0xFFFFFFFFu, p0, 2);
            p1 += __shfl_xor_sync(0xFFFFFFFFu, p1, 1);
            p1 += __shfl_xor_sync(0xFFFFFFFFu, p1, 2);
            if (t4 == 0) {
                const int R = wr * 32 + mt * 16;
                outp[m0 + R + gid]     = p0 + bias2;
                outp[m0 + R + gid + 8] = p1 + bias2;
            }
        }
    }
    __syncthreads();

    // ---- Layer 2: obs = A1(128x128) @ dec_w2^T, two N-halves of 128 ----
    for (int half = 0; half < 2; ++half) {
        for (int i = tid; i < 128 * 128; i += 512) {
            const int n = i >> 7, k = i & 127;
            sm.Wbuf[k * LDW2 + n] = dec_w2[(half * 128 + n) * 128 + k];
        }
        __syncthreads();

        float acc2[2][4][4];
        #pragma unroll
        for (int mt = 0; mt < 2; ++mt)
            #pragma unroll
            for (int nt = 0; nt < 4; ++nt)
                #pragma unroll
                for (int q = 0; q < 4; ++q) acc2[mt][nt][q] = 0.f;

        #pragma unroll
        for (int ks = 0; ks < 16; ++ks) {
            const int k0 = ks * 8;
            uint32_t ah[2][4], al[2][4];
            #pragma unroll
            for (int mt = 0; mt < 2; ++mt) {
                const int R = wr * 32 + mt * 16;
                split_tf32(sm.A1[R + gid][k0 + t4],         ah[mt][0], al[mt][0]);
                split_tf32(sm.A1[R + gid + 8][k0 + t4],     ah[mt][1], al[mt][1]);
                split_tf32(sm.A1[R + gid][k0 + t4 + 4],     ah[mt][2], al[mt][2]);
                split_tf32(sm.A1[R + gid + 8][k0 + t4 + 4], ah[mt][3], al[mt][3]);
            }
            #pragma unroll
            for (int nt = 0; nt < 4; ++nt) {
                const int n0 = wc * 32 + nt * 8;
                uint32_t bh0, bl0, bh1, bl1;
                split_tf32(sm.Wbuf[(k0 + t4) * LDW2 + n0 + gid], bh0, bl0);
                split_tf32(sm.Wbuf[(k0 + t4 + 4) * LDW2 + n0 + gid], bh1, bl1);
                #pragma unroll
                for (int mt = 0; mt < 2; ++mt) {
                    mma_tf32(acc2[mt][nt], ah[mt], bh0, bh1);
                    mma_tf32(acc2[mt][nt], al[mt], bh0, bh1);
                    mma_tf32(acc2[mt][nt], ah[mt], bl0, bl1);
                }
            }
        }

        #pragma unroll
        for (int mt = 0; mt < 2; ++mt) {
            const int R = wr * 32 + mt * 16;
            #pragma unroll
            for (int nt = 0; nt < 4; ++nt) {
                const int cg = half * 128 + wc * 32 + nt * 8 + t4 * 2;
                const float b0v = sm.b2s[cg], b1v = sm.b2s[cg + 1];
                float2 lo = make_float2(acc2[mt][nt][0] + b0v, acc2[mt][nt][1] + b1v);
                float2 hi = make_float2(acc2[mt][nt][2] + b0v, acc2[mt][nt][3] + b1v);
                *reinterpret_cast<float2*>(&obs[(long)(m0 + R + gid) * OO + cg]) = lo;
                *reinterpret_cast<float2*>(&obs[(long)(m0 + R + gid + 8) * OO + cg]) = hi;
            }
        }
        __syncthreads();
    }
}

// ---------------------------------------------------------------------------
extern "C" void kernel_launch(void* const* d_in, const int* in_sizes, int n_in,
                              void* d_out, int out_size) {
    const float* initial_state = (const float*)d_in[0];
    const float* actions = (const float*)d_in[1];
    const float* W_ih = (const float*)d_in[2];
    const float* W_hh = (const float*)d_in[3];
    const float* b_ih = (const float*)d_in[4];
    const float* b_hh = (const float*)d_in[5];
    const float* dec_w1 = (const float*)d_in[6];
    const float* dec_b1 = (const float*)d_in[7];
    const float* dec_w2 = (const float*)d_in[8];
    const float* dec_b2 = (const float*)d_in[9];
    const float* rew_w1 = (const float*)d_in[10];
    const float* rew_b1 = (const float*)d_in[11];
    const float* rew_w2 = (const float*)d_in[12];
    const float* rew_b2 = (const float*)d_in[13];
    const float* saf_w1 = (const float*)d_in[14];
    const float* saf_b1 = (const float*)d_in[15];
    const float* saf_w2 = (const float*)d_in[16];
    const float* saf_b2 = (const float*)d_in[17];

    float* out = (float*)d_out;
    float* states = out;
    float* obs = out + (long)BB * (TT + 1) * SS;
    float* rew = obs + (long)BB * TT * OO;
    float* saf = rew + (long)BB * TT;

    cudaFuncSetAttribute(scan_kernel, cudaFuncAttributeMaxDynamicSharedMemorySize,
                         (int)sizeof(ScanSmem));
    cudaFuncSetAttribute(heads_kernel, cudaFuncAttributeMaxDynamicSharedMemorySize,
                         (int)sizeof(HeadSmem));

    scan_kernel<<<BB / 16, 256, sizeof(ScanSmem)>>>(
        initial_state, actions, W_ih, W_hh, b_ih, b_hh, states);
    heads_kernel<<<(BB * TT) / 128, 512, sizeof(HeadSmem)>>>(
        states, dec_w1, dec_b1, dec_w2, dec_b2,
        rew_w1, rew_b1, rew_w2, rew_b2,
        saf_w1, saf_b1, saf_w2, saf_b2,
        obs, rew, saf);
}

// round 4
// speedup vs baseline: 2.0396x; 2.0396x over previous
#include <cuda_runtime.h>
#include <cstdint>
#include <math.h>

#define BB 2048
#define TT 128
#define SS 64
#define AA 32
#define G3 192
#define HH 128
#define OO 256

#define DEV __device__ __forceinline__

DEV uint32_t tf32b(float x) {
    uint32_t u;
    asm("cvt.rna.tf32.f32 %0, %1;" : "=r"(u) : "f"(x));
    return u;
}
DEV float tf32r(float x) { return __uint_as_float(tf32b(x)); }

DEV void split_tf32(float x, uint32_t& hi, uint32_t& lo) {
    asm("cvt.rna.tf32.f32 %0, %1;" : "=r"(hi) : "f"(x));
    float l = x - __uint_as_float(hi);
    asm("cvt.rna.tf32.f32 %0, %1;" : "=r"(lo) : "f"(l));
}

DEV void mma_tf32(float* d, const uint32_t* a, uint32_t b0, uint32_t b1) {
    asm volatile(
        "mma.sync.aligned.m16n8k8.row.col.f32.tf32.tf32.f32 "
        "{%0,%1,%2,%3}, {%4,%5,%6,%7}, {%8,%9}, {%0,%1,%2,%3};"
        : "+f"(d[0]), "+f"(d[1]), "+f"(d[2]), "+f"(d[3])
        : "r"(a[0]), "r"(a[1]), "r"(a[2]), "r"(a[3]), "r"(b0), "r"(b1));
}

// ---------------------------------------------------------------------------
// Kernel 1: GRU scan via tensor cores (tf32x3). 128 CTAs x 16 rows, 256 thr.
// Warp w owns gate-output cols [8w, 8w+8). B-hi fragments live in registers;
// B-lo (tf32 residual) in smem. One barrier per step; h carried in regs.
// ---------------------------------------------------------------------------
struct ScanSmem {
    float h[2][16][68];    // double-buffered hidden state (A-fragment source)
    float a[2][16][36];    // double-buffered action tile
    float loI[96][200];    // tf32 residual of W_ih^T  [k][n]
    float loH[64][200];    // tf32 residual of W_hh^T  [k][n]
};

__global__ void __launch_bounds__(256, 1)
scan_kernel(const float* __restrict__ initial_state,
            const float* __restrict__ actions,
            const float* __restrict__ W_ih,
            const float* __restrict__ W_hh,
            const float* __restrict__ b_ih,
            const float* __restrict__ b_hh,
            float* __restrict__ states) {
    extern __shared__ char smem_raw[];
    ScanSmem& sm = *reinterpret_cast<ScanSmem*>(smem_raw);
    const int tid = threadIdx.x;
    const int w = tid >> 5;
    const int lane = tid & 31;
    const int gid = lane >> 2;
    const int t4 = lane & 3;
    const int b0 = blockIdx.x * 16;

    // ---- prologue: residual (lo) weight arrays in smem ----
    for (int i = tid; i < G3 * 96; i += 256) {
        const int n = i / 96, k = i % 96;
        const float v = W_ih[i];
        sm.loI[k][n] = tf32r(v - tf32r(v));
    }
    for (int i = tid; i < G3 * 64; i += 256) {
        const int n = i / 64, k = i % 64;
        const float v = W_hh[i];
        sm.loH[k][n] = tf32r(v - tf32r(v));
    }

    // ---- B-hi fragments in registers (static across all 128 steps) ----
    // ti: 0 -> r-gate cols, 1 -> z-gate, 2 -> n-gate. n = w*8 + ti*64 + gid.
    uint32_t BI[3][12][2], BH[3][8][2];
    #pragma unroll
    for (int ti = 0; ti < 3; ++ti) {
        const int n = w * 8 + ti * 64 + gid;
        #pragma unroll
        for (int kc = 0; kc < 12; ++kc) {
            BI[ti][kc][0] = tf32b(W_ih[n * 96 + kc * 8 + t4]);
            BI[ti][kc][1] = tf32b(W_ih[n * 96 + kc * 8 + t4 + 4]);
        }
        #pragma unroll
        for (int kc = 0; kc < 8; ++kc) {
            BH[ti][kc][0] = tf32b(W_hh[n * 64 + kc * 8 + t4]);
            BH[ti][kc][1] = tf32b(W_hh[n * 64 + kc * 8 + t4 + 4]);
        }
    }

    // ---- biases for this thread's cols c, c+1 ----
    const int c = w * 8 + t4 * 2;
    const float br_[2]  = {b_ih[c] + b_hh[c],           b_ih[c + 1] + b_hh[c + 1]};
    const float bz_[2]  = {b_ih[64 + c] + b_hh[64 + c], b_ih[65 + c] + b_hh[65 + c]};
    const float biN_[2] = {b_ih[128 + c], b_ih[129 + c]};
    const float bhN_[2] = {b_hh[128 + c], b_hh[129 + c]};

    // ---- init h (smem + this thread's register cells) and states[:,0,:] ----
    for (int i = tid; i < 16 * SS; i += 256) {
        const int r = i >> 6, k = i & 63;
        const float v = initial_state[(long)(b0 + r) * SS + k];
        sm.h[0][r][k] = v;
        states[(long)(b0 + r) * ((TT + 1) * SS) + k] = v;
    }
    float hreg[4];
    hreg[0] = initial_state[(long)(b0 + gid) * SS + c];
    hreg[1] = initial_state[(long)(b0 + gid) * SS + c + 1];
    hreg[2] = initial_state[(long)(b0 + gid + 8) * SS + c];
    hreg[3] = initial_state[(long)(b0 + gid + 8) * SS + c + 1];

    // stage actions for t = 0
    const int pr = tid >> 4, pc = (tid & 15) * 2;
    {
        const float2 v = *reinterpret_cast<const float2*>(
            &actions[((long)(b0 + pr) * TT) * AA + pc]);
        sm.a[0][pr][pc] = v.x; sm.a[0][pr][pc + 1] = v.y;
    }
    __syncthreads();

    for (int t = 0; t < TT; ++t) {
        const int cur = t & 1, nxt = cur ^ 1;
        const bool dopref = (t + 1 < TT);
        float2 pref = make_float2(0.f, 0.f);
        if (dopref)
            pref = *reinterpret_cast<const float2*>(
                &actions[((long)(b0 + pr) * TT + (t + 1)) * AA + pc]);

        float aR[4]  = {0.f, 0.f, 0.f, 0.f};
        float aZ[4]  = {0.f, 0.f, 0.f, 0.f};
        float aNI[4] = {0.f, 0.f, 0.f, 0.f};
        float aNH[4] = {0.f, 0.f, 0.f, 0.f};

        #pragma unroll
        for (int kc = 0; kc < 12; ++kc) {
            float x0, x1, x2, x3;
            if (kc < 8) {
                x0 = sm.h[cur][gid][kc * 8 + t4];
                x1 = sm.h[cur][gid + 8][kc * 8 + t4];
                x2 = sm.h[cur][gid][kc * 8 + t4 + 4];
                x3 = sm.h[cur][gid + 8][kc * 8 + t4 + 4];
            } else {
                const int ka = (kc - 8) * 8;
                x0 = sm.a[cur][gid][ka + t4];
                x1 = sm.a[cur][gid + 8][ka + t4];
                x2 = sm.a[cur][gid][ka + t4 + 4];
                x3 = sm.a[cur][gid + 8][ka + t4 + 4];
            }
            uint32_t ah[4], al[4];
            split_tf32(x0, ah[0], al[0]);
            split_tf32(x1, ah[1], al[1]);
            split_tf32(x2, ah[2], al[2]);
            split_tf32(x3, ah[3], al[3]);

            #pragma unroll
            for (int ti = 0; ti < 3; ++ti) {
                float* acc = (ti == 0) ? aR : (ti == 1) ? aZ : aNI;
                const int n = w * 8 + ti * 64 + gid;
                const uint32_t bl0 = __float_as_uint(sm.loI[kc * 8 + t4][n]);
                const uint32_t bl1 = __float_as_uint(sm.loI[kc * 8 + t4 + 4][n]);
                mma_tf32(acc, ah, BI[ti][kc][0], BI[ti][kc][1]);
                mma_tf32(acc, al, BI[ti][kc][0], BI[ti][kc][1]);
                mma_tf32(acc, ah, bl0, bl1);
            }
            if (kc < 8) {
                #pragma unroll
                for (int ti = 0; ti < 3; ++ti) {
                    float* acc = (ti == 0) ? aR : (ti == 1) ? aZ : aNH;
                    const int n = w * 8 + ti * 64 + gid;
                    const uint32_t bl0 = __float_as_uint(sm.loH[kc * 8 + t4][n]);
                    const uint32_t bl1 = __float_as_uint(sm.loH[kc * 8 + t4 + 4][n]);
                    mma_tf32(acc, ah, BH[ti][kc][0], BH[ti][kc][1]);
                    mma_tf32(acc, al, BH[ti][kc][0], BH[ti][kc][1]);
                    mma_tf32(acc, ah, bl0, bl1);
                }
            }
        }

        // ---- gates (in registers; thread owns rows {gid,gid+8} x cols {c,c+1}) ----
        #pragma unroll
        for (int v = 0; v < 4; ++v) {
            const int p = v & 1;
            const float sr = aR[v] + br_[p];
            const float sz = aZ[v] + bz_[p];
            const float rg = __fdividef(1.f, 1.f + __expf(-sr));
            const float zg = __fdividef(1.f, 1.f + __expf(-sz));
            const float narg = aNI[v] + biN_[p] + rg * (aNH[v] + bhN_[p]);
            const float e2 = __expf(2.f * narg);
            const float ng = 1.f - __fdividef(2.f, e2 + 1.f);
            hreg[v] = (1.f - zg) * ng + zg * hreg[v];
        }

        const float2 h01 = make_float2(hreg[0], hreg[1]);
        const float2 h23 = make_float2(hreg[2], hreg[3]);
        *reinterpret_cast<float2*>(&sm.h[nxt][gid][c]) = h01;
        *reinterpret_cast<float2*>(&sm.h[nxt][gid + 8][c]) = h23;
        *reinterpret_cast<float2*>(
            &states[((long)(b0 + gid) * (TT + 1) + t + 1) * SS + c]) = h01;
        *reinterpret_cast<float2*>(
            &states[((long)(b0 + gid + 8) * (TT + 1) + t + 1) * SS + c]) = h23;
        if (dopref) { sm.a[nxt][pr][pc] = pref.x; sm.a[nxt][pr][pc + 1] = pref.y; }
        __syncthreads();
    }
}

// ---------------------------------------------------------------------------
// Kernel 2: heads, single-pass tf32 (inputs pre-rounded at smem store).
// 2048 CTAs x 128 rows, 512 threads (16 warps).
// ---------------------------------------------------------------------------
#define LDX 68
#define LDA1 132
#define LDW1 264
#define LDW2 136

struct HeadSmem {
    float X[128][LDX];
    float A1[128][LDA1];
    float Wbuf[128 * LDW2];  // L1 uses [64][LDW1], L2 uses [128][LDW2]
    float b1s[256];
    float b2s[256];
    float w2r[64];
    float w2s[64];
};

__global__ void __launch_bounds__(512, 1)
heads_kernel(const float* __restrict__ states,
             const float* __restrict__ dec_w1, const float* __restrict__ dec_b1,
             const float* __restrict__ dec_w2, const float* __restrict__ dec_b2,
             const float* __restrict__ rew_w1, const float* __restrict__ rew_b1,
             const float* __restrict__ rew_w2, const float* __restrict__ rew_b2,
             const float* __restrict__ saf_w1, const float* __restrict__ saf_b1,
             const float* __restrict__ saf_w2, const float* __restrict__ saf_b2,
             float* __restrict__ obs, float* __restrict__ rew,
             float* __restrict__ saf) {
    extern __shared__ char smem_raw[];
    HeadSmem& sm = *reinterpret_cast<HeadSmem*>(smem_raw);
    const int tid = threadIdx.x;
    const int m0 = blockIdx.x * 128;

    for (int i = tid; i < 128 * 16; i += 512) {
        const int r = i >> 4, c4 = (i & 15) * 4;
        const int m = m0 + r, b = m >> 7, t = m & 127;
        const float4 v = *reinterpret_cast<const float4*>(
            &states[((long)b * (TT + 1) + t + 1) * SS + c4]);
        sm.X[r][c4 + 0] = tf32r(v.x);
        sm.X[r][c4 + 1] = tf32r(v.y);
        sm.X[r][c4 + 2] = tf32r(v.z);
        sm.X[r][c4 + 3] = tf32r(v.w);
    }
    for (int i = tid; i < 256 * 64; i += 512) {
        const int n = i >> 6, k = i & 63;
        float wv;
        if (n < 128)      wv = dec_w1[n * 64 + k];
        else if (n < 192) wv = rew_w1[(n - 128) * 64 + k];
        else              wv = saf_w1[(n - 192) * 64 + k];
        sm.Wbuf[k * LDW1 + n] = tf32r(wv);
    }
    for (int i = tid; i < 256; i += 512) {
        sm.b1s[i] = (i < 128) ? dec_b1[i] : ((i < 192) ? rew_b1[i - 128] : saf_b1[i - 192]);
        sm.b2s[i] = dec_b2[i];
    }
    for (int i = tid; i < 64; i += 512) { sm.w2r[i] = rew_w2[i]; sm.w2s[i] = saf_w2[i]; }
    __syncthreads();

    const int lane = tid & 31;
    const int w = tid >> 5;
    const int wr = w & 3;
    const int wc = w >> 2;
    const int gid = lane >> 2;
    const int t4 = lane & 3;

    // ---- Layer 1: (128x64) @ (64x256), single-pass tf32 ----
    float acc[2][8][4];
    #pragma unroll
    for (int mt = 0; mt < 2; ++mt)
        #pragma unroll
        for (int nt = 0; nt < 8; ++nt)
            #pragma unroll
            for (int q = 0; q < 4; ++q) acc[mt][nt][q] = 0.f;

    #pragma unroll
    for (int ks = 0; ks < 8; ++ks) {
        const int k0 = ks * 8;
        uint32_t a[2][4];
        #pragma unroll
        for (int mt = 0; mt < 2; ++mt) {
            const int R = wr * 32 + mt * 16;
            a[mt][0] = __float_as_uint(sm.X[R + gid][k0 + t4]);
            a[mt][1] = __float_as_uint(sm.X[R + gid + 8][k0 + t4]);
            a[mt][2] = __float_as_uint(sm.X[R + gid][k0 + t4 + 4]);
            a[mt][3] = __float_as_uint(sm.X[R + gid + 8][k0 + t4 + 4]);
        }
        #pragma unroll
        for (int nt = 0; nt < 8; ++nt) {
            const int n0 = wc * 64 + nt * 8;
            const uint32_t b0v = __float_as_uint(sm.Wbuf[(k0 + t4) * LDW1 + n0 + gid]);
            const uint32_t b1v = __float_as_uint(sm.Wbuf[(k0 + t4 + 4) * LDW1 + n0 + gid]);
            mma_tf32(acc[0][nt], a[0], b0v, b1v);
            mma_tf32(acc[1][nt], a[1], b0v, b1v);
        }
    }

    if (wc < 2) {
        #pragma unroll
        for (int mt = 0; mt < 2; ++mt) {
            const int R = wr * 32 + mt * 16;
            #pragma unroll
            for (int nt = 0; nt < 8; ++nt) {
                const int col = wc * 64 + nt * 8 + t4 * 2;
                const float bA = sm.b1s[col], bBv = sm.b1s[col + 1];
                sm.A1[R + gid][col]         = tf32r(fmaxf(acc[mt][nt][0] + bA, 0.f));
                sm.A1[R + gid][col + 1]     = tf32r(fmaxf(acc[mt][nt][1] + bBv, 0.f));
                sm.A1[R + gid + 8][col]     = tf32r(fmaxf(acc[mt][nt][2] + bA, 0.f));
                sm.A1[R + gid + 8][col + 1] = tf32r(fmaxf(acc[mt][nt][3] + bBv, 0.f));
            }
        }
    } else {
        const bool is_rew = (wc == 2);
        const float* w2v = is_rew ? sm.w2r : sm.w2s;
        const int bbase = is_rew ? 128 : 192;
        const float bias2 = is_rew ? rew_b2[0] : saf_b2[0];
        float* outp = is_rew ? rew : saf;
        #pragma unroll
        for (int mt = 0; mt < 2; ++mt) {
            float p0 = 0.f, p1 = 0.f;
            #pragma unroll
            for (int nt = 0; nt < 8; ++nt) {
                const int l = nt * 8 + t4 * 2;
                const float bA = sm.b1s[bbase + l], bBv = sm.b1s[bbase + l + 1];
                const float v00 = fmaxf(acc[mt][nt][0] + bA, 0.f);
                const float v01 = fmaxf(acc[mt][nt][1] + bBv, 0.f);
                const float v10 = fmaxf(acc[mt][nt][2] + bA, 0.f);
                const float v11 = fmaxf(acc[mt][nt][3] + bBv, 0.f);
                p0 = fmaf(v00, w2v[l], fmaf(v01, w2v[l + 1], p0));
                p1 = fmaf(v10, w2v[l], fmaf(v11, w2v[l + 1], p1));
            }
            p0 += __shfl_xor_sync(0xFFFFFFFFu, p0, 1);
            p0 += __shfl_xor_sync(0xFFFFFFFFu, p0, 2);
            p1 += __shfl_xor_sync(0xFFFFFFFFu, p1, 1);
            p1 += __shfl_xor_sync(0xFFFFFFFFu, p1, 2);
            if (t4 == 0) {
                const int R = wr * 32 + mt * 16;
                outp[m0 + R + gid]     = p0 + bias2;
                outp[m0 + R + gid + 8] = p1 + bias2;
            }
        }
    }
    __syncthreads();

    // ---- Layer 2: obs = A1(128x128) @ dec_w2^T, two N-halves of 128 ----
    for (int half = 0; half < 2; ++half) {
        for (int i = tid; i < 128 * 128; i += 512) {
            const int n = i >> 7, k = i & 127;
            sm.Wbuf[k * LDW2 + n] = tf32r(dec_w2[(half * 128 + n) * 128 + k]);
        }
        __syncthreads();

        float acc2[2][4][4];
        #pragma unroll
        for (int mt = 0; mt < 2; ++mt)
            #pragma unroll
            for (int nt = 0; nt < 4; ++nt)
                #pragma unroll
                for (int q = 0; q < 4; ++q) acc2[mt][nt][q] = 0.f;

        #pragma unroll
        for (int ks = 0; ks < 16; ++ks) {
            const int k0 = ks * 8;
            uint32_t a[2][4];
            #pragma unroll
            for (int mt = 0; mt < 2; ++mt) {
                const int R = wr * 32 + mt * 16;
                a[mt][0] = __float_as_uint(sm.A1[R + gid][k0 + t4]);
                a[mt][1] = __float_as_uint(sm.A1[R + gid + 8][k0 + t4]);
                a[mt][2] = __float_as_uint(sm.A1[R + gid][k0 + t4 + 4]);
                a[mt][3] = __float_as_uint(sm.A1[R + gid + 8][k0 + t4 + 4]);
            }
            #pragma unroll
            for (int nt = 0; nt < 4; ++nt) {
                const int n0 = wc * 32 + nt * 8;
                const uint32_t b0v = __float_as_uint(sm.Wbuf[(k0 + t4) * LDW2 + n0 + gid]);
                const uint32_t b1v = __float_as_uint(sm.Wbuf[(k0 + t4 + 4) * LDW2 + n0 + gid]);
                mma_tf32(acc2[0][nt], a[0], b0v, b1v);
                mma_tf32(acc2[1][nt], a[1], b0v, b1v);
            }
        }

        #pragma unroll
        for (int mt = 0; mt < 2; ++mt) {
            const int R = wr * 32 + mt * 16;
            #pragma unroll
            for (int nt = 0; nt < 4; ++nt) {
                const int cg = half * 128 + wc * 32 + nt * 8 + t4 * 2;
                const float b0v = sm.b2s[cg], b1v = sm.b2s[cg + 1];
                float2 lo = make_float2(acc2[mt][nt][0] + b0v, acc2[mt][nt][1] + b1v);
                float2 hi = make_float2(acc2[mt][nt][2] + b0v, acc2[mt][nt][3] + b1v);
                *reinterpret_cast<float2*>(&obs[(long)(m0 + R + gid) * OO + cg]) = lo;
                *reinterpret_cast<float2*>(&obs[(long)(m0 + R + gid + 8) * OO + cg]) = hi;
            }
        }
        __syncthreads();
    }
}

// ---------------------------------------------------------------------------
extern "C" void kernel_launch(void* const* d_in, const int* in_sizes, int n_in,
                              void* d_out, int out_size) {
    const float* initial_state = (const float*)d_in[0];
    const float* actions = (const float*)d_in[1];
    const float* W_ih = (const float*)d_in[2];
    const float* W_hh = (const float*)d_in[3];
    const float* b_ih = (const float*)d_in[4];
    const float* b_hh = (const float*)d_in[5];
    const float* dec_w1 = (const float*)d_in[6];
    const float* dec_b1 = (const float*)d_in[7];
    const float* dec_w2 = (const float*)d_in[8];
    const float* dec_b2 = (const float*)d_in[9];
    const float* rew_w1 = (const float*)d_in[10];
    const float* rew_b1 = (const float*)d_in[11];
    const float* rew_w2 = (const float*)d_in[12];
    const float* rew_b2 = (const float*)d_in[13];
    const float* saf_w1 = (const float*)d_in[14];
    const float* saf_b1 = (const float*)d_in[15];
    const float* saf_w2 = (const float*)d_in[16];
    const float* saf_b2 = (const float*)d_in[17];

    float* out = (float*)d_out;
    float* states = out;
    float* obs = out + (long)BB * (TT + 1) * SS;
    float* rew = obs + (long)BB * TT * OO;
    float* saf = rew + (long)BB * TT;

    cudaFuncSetAttribute(scan_kernel, cudaFuncAttributeMaxDynamicSharedMemorySize,
                         (int)sizeof(ScanSmem));
    cudaFuncSetAttribute(heads_kernel, cudaFuncAttributeMaxDynamicSharedMemorySize,
                         (int)sizeof(HeadSmem));

    scan_kernel<<<BB / 16, 256, sizeof(ScanSmem)>>>(
        initial_state, actions, W_ih, W_hh, b_ih, b_hh, states);
    heads_kernel<<<(BB * TT) / 128, 512, sizeof(HeadSmem)>>>(
        states, dec_w1, dec_b1, dec_w2, dec_b2,
        rew_w1, rew_b1, rew_w2, rew_b2,
        saf_w1, saf_b1, saf_w2, saf_b2,
        obs, rew, saf);
}

// round 7
// speedup vs baseline: 2.0974x; 1.0283x over previous
#include <cuda_runtime.h>
#include <cstdint>
#include <math.h>

#define BB 2048
#define TT 128
#define SS 64
#define AA 32
#define G3 192
#define HH 128
#define OO 256

#define DEV __device__ __forceinline__

DEV uint32_t tf32b(float x) {
    uint32_t u;
    asm("cvt.rna.tf32.f32 %0, %1;" : "=r"(u) : "f"(x));
    return u;
}
DEV float tf32r(float x) { return __uint_as_float(tf32b(x)); }

// packed pair index: element u (0..7) of an 8-col group -> slot in float2-pair array
DEV int pidx(int u) { return (u < 4) ? (u << 1) : (((u - 4) << 1) | 1); }

DEV void mma_tf32(float* d, const uint32_t* a, uint32_t b0, uint32_t b1) {
    asm volatile(
        "mma.sync.aligned.m16n8k8.row.col.f32.tf32.tf32.f32 "
        "{%0,%1,%2,%3}, {%4,%5,%6,%7}, {%8,%9}, {%0,%1,%2,%3};"
        : "+f"(d[0]), "+f"(d[1]), "+f"(d[2]), "+f"(d[3])
        : "r"(a[0]), "r"(a[1]), "r"(a[2]), "r"(a[3]), "r"(b0), "r"(b1));
}

// ---------------------------------------------------------------------------
// Kernel 1: GRU scan, tensor cores tf32x3. 128 CTAs x 16 rows, 256 threads.
// h/a tiles pre-split (hi/lo) and pair-packed in smem; B-hi in registers.
// ---------------------------------------------------------------------------
struct ScanSmem {
    float hh[2][8][16][8];    // hi of h, packed pairs
    float hl[2][8][16][8];    // lo of h
    float ah2[2][4][16][8];   // hi of actions
    float al2[2][4][16][8];   // lo of actions
    float loIp[12][192][8];   // lo of W_ih^T, packed pairs  [kc][n][slot]
    float loHp[8][192][8];    // lo of W_hh^T
};

__global__ void __launch_bounds__(256, 1)
scan_kernel(const float* __restrict__ initial_state,
            const float* __restrict__ actions,
            const float* __restrict__ W_ih,
            const float* __restrict__ W_hh,
            const float* __restrict__ b_ih,
            const float* __restrict__ b_hh,
            float* __restrict__ states) {
    extern __shared__ char smem_raw[];
    ScanSmem& sm = *reinterpret_cast<ScanSmem*>(smem_raw);
    const int tid = threadIdx.x;
    const int w = tid >> 5;
    const int lane = tid & 31;
    const int gid = lane >> 2;
    const int t4 = lane & 3;
    const int b0 = blockIdx.x * 16;

    // residual (lo) weights, packed
    for (int i = tid; i < G3 * 96; i += 256) {
        const int n = i / 96, k = i % 96;
        const float v = W_ih[i];
        sm.loIp[k >> 3][n][pidx(k & 7)] = tf32r(v - tf32r(v));
    }
    for (int i = tid; i < G3 * 64; i += 256) {
        const int n = i / 64, k = i % 64;
        const float v = W_hh[i];
        sm.loHp[k >> 3][n][pidx(k & 7)] = tf32r(v - tf32r(v));
    }

    // B-hi fragments in registers (static all steps). ti: 0=r,1=z,2=n gate.
    uint32_t BI[3][12][2], BH[3][8][2];
    #pragma unroll
    for (int ti = 0; ti < 3; ++ti) {
        const int n = w * 8 + ti * 64 + gid;
        #pragma unroll
        for (int kc = 0; kc < 12; ++kc) {
            BI[ti][kc][0] = tf32b(W_ih[n * 96 + kc * 8 + t4]);
            BI[ti][kc][1] = tf32b(W_ih[n * 96 + kc * 8 + t4 + 4]);
        }
        #pragma unroll
        for (int kc = 0; kc < 8; ++kc) {
            BH[ti][kc][0] = tf32b(W_hh[n * 64 + kc * 8 + t4]);
            BH[ti][kc][1] = tf32b(W_hh[n * 64 + kc * 8 + t4 + 4]);
        }
    }

    const int c = w * 8 + t4 * 2;
    const float br_[2]  = {b_ih[c] + b_hh[c],           b_ih[c + 1] + b_hh[c + 1]};
    const float bz_[2]  = {b_ih[64 + c] + b_hh[64 + c], b_ih[65 + c] + b_hh[65 + c]};
    const float biN_[2] = {b_ih[128 + c], b_ih[129 + c]};
    const float bhN_[2] = {b_hh[128 + c], b_hh[129 + c]};

    // init h (split+packed) and states[:,0,:]
    for (int i = tid; i < 16 * SS; i += 256) {
        const int r = i >> 6, k = i & 63;
        const float v = initial_state[(long)(b0 + r) * SS + k];
        states[(long)(b0 + r) * ((TT + 1) * SS) + k] = v;
        const float hi = tf32r(v);
        sm.hh[0][k >> 3][r][pidx(k & 7)] = hi;
        sm.hl[0][k >> 3][r][pidx(k & 7)] = tf32r(v - hi);
    }
    float hreg[4];
    hreg[0] = initial_state[(long)(b0 + gid) * SS + c];
    hreg[1] = initial_state[(long)(b0 + gid) * SS + c + 1];
    hreg[2] = initial_state[(long)(b0 + gid + 8) * SS + c];
    hreg[3] = initial_state[(long)(b0 + gid + 8) * SS + c + 1];

    // stage actions t=0, split+packed
    const int pr = tid >> 4, pc = (tid & 15) * 2;
    {
        const float2 v = *reinterpret_cast<const float2*>(
            &actions[((long)(b0 + pr) * TT) * AA + pc]);
        float hx = tf32r(v.x);
        sm.ah2[0][pc >> 3][pr][pidx(pc & 7)] = hx;
        sm.al2[0][pc >> 3][pr][pidx(pc & 7)] = tf32r(v.x - hx);
        hx = tf32r(v.y);
        sm.ah2[0][(pc + 1) >> 3][pr][pidx((pc + 1) & 7)] = hx;
        sm.al2[0][(pc + 1) >> 3][pr][pidx((pc + 1) & 7)] = tf32r(v.y - hx);
    }
    __syncthreads();

    const int i0w = pidx(t4 * 2);
    const int i1w = pidx(t4 * 2 + 1);

    for (int t = 0; t < TT; ++t) {
        const int cur = t & 1, nxt = cur ^ 1;
        const bool dopref = (t + 1 < TT);
        float2 pref = make_float2(0.f, 0.f);
        if (dopref)
            pref = *reinterpret_cast<const float2*>(
                &actions[((long)(b0 + pr) * TT + (t + 1)) * AA + pc]);

        float aR[4]  = {0.f, 0.f, 0.f, 0.f};
        float aZ[4]  = {0.f, 0.f, 0.f, 0.f};
        float aNI[4] = {0.f, 0.f, 0.f, 0.f};
        float aNH[4] = {0.f, 0.f, 0.f, 0.f};

        #pragma unroll
        for (int kc = 0; kc < 12; ++kc) {
            float2 h0, h1, l0, l1;
            if (kc < 8) {
                h0 = *reinterpret_cast<const float2*>(&sm.hh[cur][kc][gid][2 * t4]);
                h1 = *reinterpret_cast<const float2*>(&sm.hh[cur][kc][gid + 8][2 * t4]);
                l0 = *reinterpret_cast<const float2*>(&sm.hl[cur][kc][gid][2 * t4]);
                l1 = *reinterpret_cast<const float2*>(&sm.hl[cur][kc][gid + 8][2 * t4]);
            } else {
                h0 = *reinterpret_cast<const float2*>(&sm.ah2[cur][kc - 8][gid][2 * t4]);
                h1 = *reinterpret_cast<const float2*>(&sm.ah2[cur][kc - 8][gid + 8][2 * t4]);
                l0 = *reinterpret_cast<const float2*>(&sm.al2[cur][kc - 8][gid][2 * t4]);
                l1 = *reinterpret_cast<const float2*>(&sm.al2[cur][kc - 8][gid + 8][2 * t4]);
            }
            uint32_t ah[4] = {__float_as_uint(h0.x), __float_as_uint(h1.x),
                              __float_as_uint(h0.y), __float_as_uint(h1.y)};
            uint32_t al[4] = {__float_as_uint(l0.x), __float_as_uint(l1.x),
                              __float_as_uint(l0.y), __float_as_uint(l1.y)};

            #pragma unroll
            for (int ti = 0; ti < 3; ++ti) {
                float* acc = (ti == 0) ? aR : (ti == 1) ? aZ : aNI;
                const int n = w * 8 + ti * 64 + gid;
                const float2 bl = *reinterpret_cast<const float2*>(&sm.loIp[kc][n][2 * t4]);
                mma_tf32(acc, ah, BI[ti][kc][0], BI[ti][kc][1]);
                mma_tf32(acc, al, BI[ti][kc][0], BI[ti][kc][1]);
                mma_tf32(acc, ah, __float_as_uint(bl.x), __float_as_uint(bl.y));
            }
            if (kc < 8) {
                #pragma unroll
                for (int ti = 0; ti < 3; ++ti) {
                    float* acc = (ti == 0) ? aR : (ti == 1) ? aZ : aNH;
                    const int n = w * 8 + ti * 64 + gid;
                    const float2 bl = *reinterpret_cast<const float2*>(&sm.loHp[kc][n][2 * t4]);
                    mma_tf32(acc, ah, BH[ti][kc][0], BH[ti][kc][1]);
                    mma_tf32(acc, al, BH[ti][kc][0], BH[ti][kc][1]);
                    mma_tf32(acc, ah, __float_as_uint(bl.x), __float_as_uint(bl.y));
                }
            }
        }

        // gates
        #pragma unroll
        for (int v = 0; v < 4; ++v) {
            const int p = v & 1;
            const float sr = aR[v] + br_[p];
            const float sz = aZ[v] + bz_[p];
            const float rg = __fdividef(1.f, 1.f + __expf(-sr));
            const float zg = __fdividef(1.f, 1.f + __expf(-sz));
            const float narg = aNI[v] + biN_[p] + rg * (aNH[v] + bhN_[p]);
            const float e2 = __expf(2.f * narg);
            const float ng = 1.f - __fdividef(2.f, e2 + 1.f);
            hreg[v] = (1.f - zg) * ng + zg * hreg[v];
        }

        // write split/packed h for next step + fp32 states
        {
            const float hi0 = tf32r(hreg[0]), hi1 = tf32r(hreg[1]);
            const float hi2 = tf32r(hreg[2]), hi3 = tf32r(hreg[3]);
            sm.hh[nxt][w][gid][i0w]     = hi0;
            sm.hh[nxt][w][gid][i1w]     = hi1;
            sm.hh[nxt][w][gid + 8][i0w] = hi2;
            sm.hh[nxt][w][gid + 8][i1w] = hi3;
            sm.hl[nxt][w][gid][i0w]     = tf32r(hreg[0] - hi0);
            sm.hl[nxt][w][gid][i1w]     = tf32r(hreg[1] - hi1);
            sm.hl[nxt][w][gid + 8][i0w] = tf32r(hreg[2] - hi2);
            sm.hl[nxt][w][gid + 8][i1w] = tf32r(hreg[3] - hi3);
        }
        *reinterpret_cast<float2*>(
            &states[((long)(b0 + gid) * (TT + 1) + t + 1) * SS + c]) =
            make_float2(hreg[0], hreg[1]);
        *reinterpret_cast<float2*>(
            &states[((long)(b0 + gid + 8) * (TT + 1) + t + 1) * SS + c]) =
            make_float2(hreg[2], hreg[3]);
        if (dopref) {
            float hx = tf32r(pref.x);
            sm.ah2[nxt][pc >> 3][pr][pidx(pc & 7)] = hx;
            sm.al2[nxt][pc >> 3][pr][pidx(pc & 7)] = tf32r(pref.x - hx);
            hx = tf32r(pref.y);
            sm.ah2[nxt][(pc + 1) >> 3][pr][pidx((pc + 1) & 7)] = hx;
            sm.al2[nxt][(pc + 1) >> 3][pr][pidx((pc + 1) & 7)] = tf32r(pref.y - hx);
        }
        __syncthreads();
    }
}

// ---------------------------------------------------------------------------
// Kernel 2: heads, single-pass tf32, packed float2 fragments, prefetched W.
// 2048 CTAs x 128 rows, 512 threads (16 warps).
// ---------------------------------------------------------------------------
struct HeadSmem {
    float Xp[8][128][8];    // packed state tile           32768 B
    float WA[16384];        // L1 weights [8][256][8] view; later W2 half1 [16][128][8]
    float A1p[16][128][8];  // packed relu(layer1)         65536 B
    float WB[16][128][8];   // W2 half0 (prefetched)       65536 B
    float b1s[256];
    float w2r[64];
    float w2s[64];
};

__global__ void __launch_bounds__(512, 1)
heads_kernel(const float* __restrict__ states,
             const float* __restrict__ dec_w1, const float* __restrict__ dec_b1,
             const float* __restrict__ dec_w2, const float* __restrict__ dec_b2,
             const float* __restrict__ rew_w1, const float* __restrict__ rew_b1,
             const float* __restrict__ rew_w2, const float* __restrict__ rew_b2,
             const float* __restrict__ saf_w1, const float* __restrict__ saf_b1,
             const float* __restrict__ saf_w2, const float* __restrict__ saf_b2,
             float* __restrict__ obs, float* __restrict__ rew,
             float* __restrict__ saf) {
    extern __shared__ char smem_raw[];
    HeadSmem& sm = *reinterpret_cast<HeadSmem*>(smem_raw);
    const int tid = threadIdx.x;
    const int m0 = blockIdx.x * 128;

    // ---- prologue staging (all overlapped, one barrier) ----
    for (int i = tid; i < 128 * 16; i += 512) {
        const int r = i >> 4, c4 = (i & 15) * 4;
        const int m = m0 + r, b = m >> 7, t = m & 127;
        const float4 v = *reinterpret_cast<const float4*>(
            &states[((long)b * (TT + 1) + t + 1) * SS + c4]);
        float* p = &sm.Xp[c4 >> 3][r][0];
        if ((c4 & 4) == 0) {
            p[0] = tf32r(v.x); p[2] = tf32r(v.y); p[4] = tf32r(v.z); p[6] = tf32r(v.w);
        } else {
            p[1] = tf32r(v.x); p[3] = tf32r(v.y); p[5] = tf32r(v.z); p[7] = tf32r(v.w);
        }
    }
    for (int i = tid; i < 256 * 64; i += 512) {
        const int n = i >> 6, k = i & 63;
        float wv;
        if (n < 128)      wv = dec_w1[n * 64 + k];
        else if (n < 192) wv = rew_w1[(n - 128) * 64 + k];
        else              wv = saf_w1[(n - 192) * 64 + k];
        sm.WA[(k >> 3) * 2048 + n * 8 + pidx(k & 7)] = tf32r(wv);
    }
    for (int i = tid; i < 128 * 128; i += 512) {   // W2 half0 prefetch
        const int n = i >> 7, k = i & 127;
        sm.WB[k >> 3][n][pidx(k & 7)] = tf32r(dec_w2[n * 128 + k]);
    }
    for (int i = tid; i < 256; i += 512)
        sm.b1s[i] = (i < 128) ? dec_b1[i] : ((i < 192) ? rew_b1[i - 128] : saf_b1[i - 192]);
    for (int i = tid; i < 64; i += 512) { sm.w2r[i] = rew_w2[i]; sm.w2s[i] = saf_w2[i]; }
    __syncthreads();

    const int lane = tid & 31;
    const int w = tid >> 5;
    const int wr = w & 3;
    const int wc = w >> 2;
    const int gid = lane >> 2;
    const int t4 = lane & 3;
    const int i0p = pidx(t4 * 2);
    const int i1p = pidx(t4 * 2 + 1);

    // ---- Layer 1: (128x64) @ (64x256) ----
    float acc[2][8][4];
    #pragma unroll
    for (int mt = 0; mt < 2; ++mt)
        #pragma unroll
        for (int nt = 0; nt < 8; ++nt)
            #pragma unroll
            for (int q = 0; q < 4; ++q) acc[mt][nt][q] = 0.f;

    #pragma unroll
    for (int ks = 0; ks < 8; ++ks) {
        uint32_t a[2][4];
        #pragma unroll
        for (int mt = 0; mt < 2; ++mt) {
            const int R = wr * 32 + mt * 16;
            const float2 f0 = *reinterpret_cast<const float2*>(&sm.Xp[ks][R + gid][2 * t4]);
            const float2 f1 = *reinterpret_cast<const float2*>(&sm.Xp[ks][R + gid + 8][2 * t4]);
            a[mt][0] = __float_as_uint(f0.x); a[mt][1] = __float_as_uint(f1.x);
            a[mt][2] = __float_as_uint(f0.y); a[mt][3] = __float_as_uint(f1.y);
        }
        #pragma unroll
        for (int nt = 0; nt < 8; ++nt) {
            const int n0 = wc * 64 + nt * 8;
            const float2 bv = *reinterpret_cast<const float2*>(
                &sm.WA[ks * 2048 + (n0 + gid) * 8 + 2 * t4]);
            mma_tf32(acc[0][nt], a[0], __float_as_uint(bv.x), __float_as_uint(bv.y));
            mma_tf32(acc[1][nt], a[1], __float_as_uint(bv.x), __float_as_uint(bv.y));
        }
    }

    if (wc < 2) {
        #pragma unroll
        for (int mt = 0; mt < 2; ++mt) {
            const int R = wr * 32 + mt * 16;
            #pragma unroll
            for (int nt = 0; nt < 8; ++nt) {
                const int ks2 = wc * 8 + nt;
                const int col = wc * 64 + nt * 8 + t4 * 2;
                const float bA = sm.b1s[col], bBv = sm.b1s[col + 1];
                sm.A1p[ks2][R + gid][i0p]     = tf32r(fmaxf(acc[mt][nt][0] + bA, 0.f));
                sm.A1p[ks2][R + gid][i1p]     = tf32r(fmaxf(acc[mt][nt][1] + bBv, 0.f));
                sm.A1p[ks2][R + gid + 8][i0p] = tf32r(fmaxf(acc[mt][nt][2] + bA, 0.f));
                sm.A1p[ks2][R + gid + 8][i1p] = tf32r(fmaxf(acc[mt][nt][3] + bBv, 0.f));
            }
        }
    } else {
        const bool is_rew = (wc == 2);
        const float* w2v = is_rew ? sm.w2r : sm.w2s;
        const int bbase = is_rew ? 128 : 192;
        const float bias2 = is_rew ? rew_b2[0] : saf_b2[0];
        float* outp = is_rew ? rew : saf;
        #pragma unroll
        for (int mt = 0; mt < 2; ++mt) {
            float p0 = 0.f, p1 = 0.f;
            #pragma unroll
            for (int nt = 0; nt < 8; ++nt) {
                const int l = nt * 8 + t4 * 2;
                const float bA = sm.b1s[bbase + l], bBv = sm.b1s[bbase + l + 1];
                const float v00 = fmaxf(acc[mt][nt][0] + bA, 0.f);
                const float v01 = fmaxf(acc[mt][nt][1] + bBv, 0.f);
                const float v10 = fmaxf(acc[mt][nt][2] + bA, 0.f);
                const float v11 = fmaxf(acc[mt][nt][3] + bBv, 0.f);
                p0 = fmaf(v00, w2v[l], fmaf(v01, w2v[l + 1], p0));
                p1 = fmaf(v10, w2v[l], fmaf(v11, w2v[l + 1], p1));
            }
            p0 += __shfl_xor_sync(0xFFFFFFFFu, p0, 1);
            p0 += __shfl_xor_sync(0xFFFFFFFFu, p0, 2);
            p1 += __shfl_xor_sync(0xFFFFFFFFu, p1, 1);
            p1 += __shfl_xor_sync(0xFFFFFFFFu, p1, 2);
            if (t4 == 0) {
                const int R = wr * 32 + mt * 16;
                outp[m0 + R + gid]     = p0 + bias2;
                outp[m0 + R + gid + 8] = p1 + bias2;
            }
        }
    }
    __syncthreads();

    // ---- Layer 2 half 0 (weights already in WB) ----
    {
        float acc2[2][4][4];
        #pragma unroll
        for (int mt = 0; mt < 2; ++mt)
            #pragma unroll
            for (int nt = 0; nt < 4; ++nt)
                #pragma unroll
                for (int q = 0; q < 4; ++q) acc2[mt][nt][q] = 0.f;

        #pragma unroll
        for (int ks = 0; ks < 16; ++ks) {
            uint32_t a[2][4];
            #pragma unroll
            for (int mt = 0; mt < 2; ++mt) {
                const int R = wr * 32 + mt * 16;
                const float2 f0 = *reinterpret_cast<const float2*>(&sm.A1p[ks][R + gid][2 * t4]);
                const float2 f1 = *reinterpret_cast<const float2*>(&sm.A1p[ks][R + gid + 8][2 * t4]);
                a[mt][0] = __float_as_uint(f0.x); a[mt][1] = __float_as_uint(f1.x);
                a[mt][2] = __float_as_uint(f0.y); a[mt][3] = __float_as_uint(f1.y);
            }
            #pragma unroll
            for (int nt = 0; nt < 4; ++nt) {
                const int n0 = wc * 32 + nt * 8;
                const float2 bv = *reinterpret_cast<const float2*>(&sm.WB[ks][n0 + gid][2 * t4]);
                mma_tf32(acc2[0][nt], a[0], __float_as_uint(bv.x), __float_as_uint(bv.y));
                mma_tf32(acc2[1][nt], a[1], __float_as_uint(bv.x), __float_as_uint(bv.y));
            }
        }
        #pragma unroll
        for (int mt = 0; mt < 2; ++mt) {
            const int R = wr * 32 + mt * 16;
            #pragma unroll
            for (int nt = 0; nt < 4; ++nt) {
                const int cg = wc * 32 + nt * 8 + t4 * 2;
                const float2 b2v = *reinterpret_cast<const float2*>(&dec_b2[cg]);
                *reinterpret_cast<float2*>(&obs[(long)(m0 + R + gid) * OO + cg]) =
                    make_float2(acc2[mt][nt][0] + b2v.x, acc2[mt][nt][1] + b2v.y);
                *reinterpret_cast<float2*>(&obs[(long)(m0 + R + gid + 8) * OO + cg]) =
                    make_float2(acc2[mt][nt][2] + b2v.x, acc2[mt][nt][3] + b2v.y);
            }
        }
    }

    // stage W2 half1 into WA (free since the post-L1 barrier)
    for (int i = tid; i < 128 * 128; i += 512) {
        const int n = i >> 7, k = i & 127;
        sm.WA[(k >> 3) * 1024 + n * 8 + pidx(k & 7)] = tf32r(dec_w2[(128 + n) * 128 + k]);
    }
    __syncthreads();

    // ---- Layer 2 half 1 ----
    {
        float acc2[2][4][4];
        #pragma unroll
        for (int mt = 0; mt < 2; ++mt)
            #pragma unroll
            for (int nt = 0; nt < 4; ++nt)
                #pragma unroll
                for (int q = 0; q < 4; ++q) acc2[mt][nt][q] = 0.f;

        #pragma unroll
        for (int ks = 0; ks < 16; ++ks) {
            uint32_t a[2][4];
            #pragma unroll
            for (int mt = 0; mt < 2; ++mt) {
                const int R = wr * 32 + mt * 16;
                const float2 f0 = *reinterpret_cast<const float2*>(&sm.A1p[ks][R + gid][2 * t4]);
                const float2 f1 = *reinterpret_cast<const float2*>(&sm.A1p[ks][R + gid + 8][2 * t4]);
                a[mt][0] = __float_as_uint(f0.x); a[mt][1] = __float_as_uint(f1.x);
                a[mt][2] = __float_as_uint(f0.y); a[mt][3] = __float_as_uint(f1.y);
            }
            #pragma unroll
            for (int nt = 0; nt < 4; ++nt) {
                const int n0 = wc * 32 + nt * 8;
                const float2 bv = *reinterpret_cast<const float2*>(
                    &sm.WA[ks * 1024 + (n0 + gid) * 8 + 2 * t4]);
                mma_tf32(acc2[0][nt], a[0], __float_as_uint(bv.x), __float_as_uint(bv.y));
                mma_tf32(acc2[1][nt], a[1], __float_as_uint(bv.x), __float_as_uint(bv.y));
            }
        }
        #pragma unroll
        for (int mt = 0; mt < 2; ++mt) {
            const int R = wr * 32 + mt * 16;
            #pragma unroll
            for (int nt = 0; nt < 4; ++nt) {
                const int cg = 128 + wc * 32 + nt * 8 + t4 * 2;
                const float2 b2v = *reinterpret_cast<const float2*>(&dec_b2[cg]);
                *reinterpret_cast<float2*>(&obs[(long)(m0 + R + gid) * OO + cg]) =
                    make_float2(acc2[mt][nt][0] + b2v.x, acc2[mt][nt][1] + b2v.y);
                *reinterpret_cast<float2*>(&obs[(long)(m0 + R + gid + 8) * OO + cg]) =
                    make_float2(acc2[mt][nt][2] + b2v.x, acc2[mt][nt][3] + b2v.y);
            }
        }
    }
}

// ---------------------------------------------------------------------------
extern "C" void kernel_launch(void* const* d_in, const int* in_sizes, int n_in,
                              void* d_out, int out_size) {
    const float* initial_state = (const float*)d_in[0];
    const float* actions = (const float*)d_in[1];
    const float* W_ih = (const float*)d_in[2];
    const float* W_hh = (const float*)d_in[3];
    const float* b_ih = (const float*)d_in[4];
    const float* b_hh = (const float*)d_in[5];
    const float* dec_w1 = (const float*)d_in[6];
    const float* dec_b1 = (const float*)d_in[7];
    const float* dec_w2 = (const float*)d_in[8];
    const float* dec_b2 = (const float*)d_in[9];
    const float* rew_w1 = (const float*)d_in[10];
    const float* rew_b1 = (const float*)d_in[11];
    const float* rew_w2 = (const float*)d_in[12];
    const float* rew_b2 = (const float*)d_in[13];
    const float* saf_w1 = (const float*)d_in[14];
    const float* saf_b1 = (const float*)d_in[15];
    const float* saf_w2 = (const float*)d_in[16];
    const float* saf_b2 = (const float*)d_in[17];

    float* out = (float*)d_out;
    float* states = out;
    float* obs = out + (long)BB * (TT + 1) * SS;
    float* rew = obs + (long)BB * TT * OO;
    float* saf = rew + (long)BB * TT;

    cudaFuncSetAttribute(scan_kernel, cudaFuncAttributeMaxDynamicSharedMemorySize,
                         (int)sizeof(ScanSmem));
    cudaFuncSetAttribute(heads_kernel, cudaFuncAttributeMaxDynamicSharedMemorySize,
                         (int)sizeof(HeadSmem));

    scan_kernel<<<BB / 16, 256, sizeof(ScanSmem)>>>(
        initial_state, actions, W_ih, W_hh, b_ih, b_hh, states);
    heads_kernel<<<(BB * TT) / 128, 512, sizeof(HeadSmem)>>>(
        states, dec_w1, dec_b1, dec_w2, dec_b2,
        rew_w1, rew_b1, rew_w2, rew_b2,
        saf_w1, saf_b1, saf_w2, saf_b2,
        obs, rew, saf);
}

// round 8
// speedup vs baseline: 2.1287x; 1.0149x over previous
#include <cuda_runtime.h>
#include <cuda_bf16.h>
#include <cstdint>
#include <math.h>

#define BB 2048
#define TT 128
#define SS 64
#define AA 32
#define G3 192
#define HH 128
#define OO 256

#define DEV __device__ __forceinline__

DEV uint32_t tf32b(float x) {
    uint32_t u;
    asm("cvt.rna.tf32.f32 %0, %1;" : "=r"(u) : "f"(x));
    return u;
}
DEV float tf32r(float x) { return __uint_as_float(tf32b(x)); }

// packed pair index: element u (0..7) of an 8-group -> slot in float2-pair array
DEV int pidx(int u) { return (u < 4) ? (u << 1) : (((u - 4) << 1) | 1); }

DEV float bfhi(float x) { return __bfloat162float(__float2bfloat16_rn(x)); }
DEV uint32_t bfpack(float x, float y) {
    __nv_bfloat162 t = __floats2bfloat162_rn(x, y);
    return *reinterpret_cast<uint32_t*>(&t);
}

DEV void mma_tf32(float* d, const uint32_t* a, uint32_t b0, uint32_t b1) {
    asm volatile(
        "mma.sync.aligned.m16n8k8.row.col.f32.tf32.tf32.f32 "
        "{%0,%1,%2,%3}, {%4,%5,%6,%7}, {%8,%9}, {%0,%1,%2,%3};"
        : "+f"(d[0]), "+f"(d[1]), "+f"(d[2]), "+f"(d[3])
        : "r"(a[0]), "r"(a[1]), "r"(a[2]), "r"(a[3]), "r"(b0), "r"(b1));
}

DEV void mma_bf16(float* d, const uint32_t* a, uint32_t b0, uint32_t b1) {
    asm volatile(
        "mma.sync.aligned.m16n8k16.row.col.f32.bf16.bf16.f32 "
        "{%0,%1,%2,%3}, {%4,%5,%6,%7}, {%8,%9}, {%0,%1,%2,%3};"
        : "+f"(d[0]), "+f"(d[1]), "+f"(d[2]), "+f"(d[3])
        : "r"(a[0]), "r"(a[1]), "r"(a[2]), "r"(a[3]), "r"(b0), "r"(b1));
}

// ---------------------------------------------------------------------------
// Kernel 1: GRU scan, bf16x3 mma.m16n8k16. 128 CTAs x 16 rows, 256 threads.
// h/a tiles pre-split (hi/lo bf16x2 pairs) in smem; B-hi in registers.
// ---------------------------------------------------------------------------
struct ScanSmem {
    uint32_t hhp[2][4][16][8];   // hi of h, bf16x2 pairs [buf][kc16][row][slot]
    uint32_t hlp[2][4][16][8];   // lo of h
    uint32_t ahp[2][2][16][8];   // hi of actions
    uint32_t alp[2][2][16][8];   // lo of actions
    uint32_t loIp[6][192][8];    // lo of W_ih^T pairs [kc16][n][slot]
    uint32_t loHp[4][192][8];    // lo of W_hh^T
};

__global__ void __launch_bounds__(256, 1)
scan_kernel(const float* __restrict__ initial_state,
            const float* __restrict__ actions,
            const float* __restrict__ W_ih,
            const float* __restrict__ W_hh,
            const float* __restrict__ b_ih,
            const float* __restrict__ b_hh,
            float* __restrict__ states) {
    extern __shared__ char smem_raw[];
    ScanSmem& sm = *reinterpret_cast<ScanSmem*>(smem_raw);
    const int tid = threadIdx.x;
    const int w = tid >> 5;
    const int lane = tid & 31;
    const int gid = lane >> 2;
    const int t4 = lane & 3;
    const int b0 = blockIdx.x * 16;

    // residual (lo) weights, packed bf16x2 pairs
    for (int i = tid; i < 192 * 48; i += 256) {
        const int n = i / 48, p = i % 48;   // p = k-pair index (k = 2p, 2p+1)
        const float v0 = W_ih[n * 96 + 2 * p];
        const float v1 = W_ih[n * 96 + 2 * p + 1];
        sm.loIp[p >> 3][n][pidx(p & 7)] = bfpack(v0 - bfhi(v0), v1 - bfhi(v1));
    }
    for (int i = tid; i < 192 * 32; i += 256) {
        const int n = i / 32, p = i % 32;
        const float v0 = W_hh[n * 64 + 2 * p];
        const float v1 = W_hh[n * 64 + 2 * p + 1];
        sm.loHp[p >> 3][n][pidx(p & 7)] = bfpack(v0 - bfhi(v0), v1 - bfhi(v1));
    }

    // B-hi fragments in registers (static). ti: 0=r,1=z,2=n gate.
    uint32_t BI[3][6][2], BH[3][4][2];
    #pragma unroll
    for (int ti = 0; ti < 3; ++ti) {
        const int n = w * 8 + ti * 64 + gid;
        #pragma unroll
        for (int kc = 0; kc < 6; ++kc) {
            const int k0 = kc * 16 + 2 * t4;
            BI[ti][kc][0] = bfpack(bfhi(W_ih[n * 96 + k0]),     bfhi(W_ih[n * 96 + k0 + 1]));
            BI[ti][kc][1] = bfpack(bfhi(W_ih[n * 96 + k0 + 8]), bfhi(W_ih[n * 96 + k0 + 9]));
        }
        #pragma unroll
        for (int kc = 0; kc < 4; ++kc) {
            const int k0 = kc * 16 + 2 * t4;
            BH[ti][kc][0] = bfpack(bfhi(W_hh[n * 64 + k0]),     bfhi(W_hh[n * 64 + k0 + 1]));
            BH[ti][kc][1] = bfpack(bfhi(W_hh[n * 64 + k0 + 8]), bfhi(W_hh[n * 64 + k0 + 9]));
        }
    }

    const int c = w * 8 + t4 * 2;
    const float br_[2]  = {b_ih[c] + b_hh[c],           b_ih[c + 1] + b_hh[c + 1]};
    const float bz_[2]  = {b_ih[64 + c] + b_hh[64 + c], b_ih[65 + c] + b_hh[65 + c]};
    const float biN_[2] = {b_ih[128 + c], b_ih[129 + c]};
    const float bhN_[2] = {b_hh[128 + c], b_hh[129 + c]};

    // init h (split+packed pairs) and states[:,0,:]
    for (int i = tid; i < 16 * 32; i += 256) {     // 16 rows x 32 pairs
        const int r = i >> 5, p = i & 31;
        const float v0 = initial_state[(long)(b0 + r) * SS + 2 * p];
        const float v1 = initial_state[(long)(b0 + r) * SS + 2 * p + 1];
        states[(long)(b0 + r) * ((TT + 1) * SS) + 2 * p]     = v0;
        states[(long)(b0 + r) * ((TT + 1) * SS) + 2 * p + 1] = v1;
        const float h0 = bfhi(v0), h1 = bfhi(v1);
        sm.hhp[0][p >> 3][r][pidx(p & 7)] = bfpack(h0, h1);
        sm.hlp[0][p >> 3][r][pidx(p & 7)] = bfpack(v0 - h0, v1 - h1);
    }
    float hreg[4];
    hreg[0] = initial_state[(long)(b0 + gid) * SS + c];
    hreg[1] = initial_state[(long)(b0 + gid) * SS + c + 1];
    hreg[2] = initial_state[(long)(b0 + gid + 8) * SS + c];
    hreg[3] = initial_state[(long)(b0 + gid + 8) * SS + c + 1];

    // stage actions t=0 (each thread: one row, one pair)
    const int pr = tid >> 4;
    const int pp = tid & 15;             // pair index 0..15 (k = 2pp, 2pp+1)
    const int akc = pp >> 3, aslot = pidx(pp & 7);
    {
        const float2 v = *reinterpret_cast<const float2*>(
            &actions[((long)(b0 + pr) * TT) * AA + 2 * pp]);
        const float h0 = bfhi(v.x), h1 = bfhi(v.y);
        sm.ahp[0][akc][pr][aslot] = bfpack(h0, h1);
        sm.alp[0][akc][pr][aslot] = bfpack(v.x - h0, v.y - h1);
    }
    __syncthreads();

    // h write-back slot for this thread's cols
    const int hkc   = (w * 4 + t4) >> 3;
    const int hslot = pidx((w * 4 + t4) & 7);

    for (int t = 0; t < TT; ++t) {
        const int cur = t & 1, nxt = cur ^ 1;
        const bool dopref = (t + 1 < TT);
        float2 pref = make_float2(0.f, 0.f);
        if (dopref)
            pref = *reinterpret_cast<const float2*>(
                &actions[((long)(b0 + pr) * TT + (t + 1)) * AA + 2 * pp]);

        float aR[4]  = {0.f, 0.f, 0.f, 0.f};
        float aZ[4]  = {0.f, 0.f, 0.f, 0.f};
        float aNI[4] = {0.f, 0.f, 0.f, 0.f};
        float aNH[4] = {0.f, 0.f, 0.f, 0.f};

        #pragma unroll
        for (int kc = 0; kc < 6; ++kc) {
            uint2 h0, h1, l0, l1;
            if (kc < 4) {
                h0 = *reinterpret_cast<const uint2*>(&sm.hhp[cur][kc][gid][2 * t4]);
                h1 = *reinterpret_cast<const uint2*>(&sm.hhp[cur][kc][gid + 8][2 * t4]);
                l0 = *reinterpret_cast<const uint2*>(&sm.hlp[cur][kc][gid][2 * t4]);
                l1 = *reinterpret_cast<const uint2*>(&sm.hlp[cur][kc][gid + 8][2 * t4]);
            } else {
                h0 = *reinterpret_cast<const uint2*>(&sm.ahp[cur][kc - 4][gid][2 * t4]);
                h1 = *reinterpret_cast<const uint2*>(&sm.ahp[cur][kc - 4][gid + 8][2 * t4]);
                l0 = *reinterpret_cast<const uint2*>(&sm.alp[cur][kc - 4][gid][2 * t4]);
                l1 = *reinterpret_cast<const uint2*>(&sm.alp[cur][kc - 4][gid + 8][2 * t4]);
            }
            const uint32_t ah[4] = {h0.x, h1.x, h0.y, h1.y};
            const uint32_t al[4] = {l0.x, l1.x, l0.y, l1.y};

            #pragma unroll
            for (int ti = 0; ti < 3; ++ti) {
                float* acc = (ti == 0) ? aR : (ti == 1) ? aZ : aNI;
                const int n = w * 8 + ti * 64 + gid;
                const uint2 bl = *reinterpret_cast<const uint2*>(&sm.loIp[kc][n][2 * t4]);
                mma_bf16(acc, ah, BI[ti][kc][0], BI[ti][kc][1]);
                mma_bf16(acc, al, BI[ti][kc][0], BI[ti][kc][1]);
                mma_bf16(acc, ah, bl.x, bl.y);
            }
            if (kc < 4) {
                #pragma unroll
                for (int ti = 0; ti < 3; ++ti) {
                    float* acc = (ti == 0) ? aR : (ti == 1) ? aZ : aNH;
                    const int n = w * 8 + ti * 64 + gid;
                    const uint2 bl = *reinterpret_cast<const uint2*>(&sm.loHp[kc][n][2 * t4]);
                    mma_bf16(acc, ah, BH[ti][kc][0], BH[ti][kc][1]);
                    mma_bf16(acc, al, BH[ti][kc][0], BH[ti][kc][1]);
                    mma_bf16(acc, ah, bl.x, bl.y);
                }
            }
        }

        // gates
        #pragma unroll
        for (int v = 0; v < 4; ++v) {
            const int p = v & 1;
            const float sr = aR[v] + br_[p];
            const float sz = aZ[v] + bz_[p];
            const float rg = __fdividef(1.f, 1.f + __expf(-sr));
            const float zg = __fdividef(1.f, 1.f + __expf(-sz));
            const float narg = aNI[v] + biN_[p] + rg * (aNH[v] + bhN_[p]);
            const float e2 = __expf(2.f * narg);
            const float ng = 1.f - __fdividef(2.f, e2 + 1.f);
            hreg[v] = (1.f - zg) * ng + zg * hreg[v];
        }

        // write split/packed h for next step + fp32 states
        {
            const float hi0 = bfhi(hreg[0]), hi1 = bfhi(hreg[1]);
            const float hi2 = bfhi(hreg[2]), hi3 = bfhi(hreg[3]);
            sm.hhp[nxt][hkc][gid][hslot]     = bfpack(hi0, hi1);
            sm.hhp[nxt][hkc][gid + 8][hslot] = bfpack(hi2, hi3);
            sm.hlp[nxt][hkc][gid][hslot]     = bfpack(hreg[0] - hi0, hreg[1] - hi1);
            sm.hlp[nxt][hkc][gid + 8][hslot] = bfpack(hreg[2] - hi2, hreg[3] - hi3);
        }
        *reinterpret_cast<float2*>(
            &states[((long)(b0 + gid) * (TT + 1) + t + 1) * SS + c]) =
            make_float2(hreg[0], hreg[1]);
        *reinterpret_cast<float2*>(
            &states[((long)(b0 + gid + 8) * (TT + 1) + t + 1) * SS + c]) =
            make_float2(hreg[2], hreg[3]);
        if (dopref) {
            const float h0 = bfhi(pref.x), h1 = bfhi(pref.y);
            sm.ahp[nxt][akc][pr][aslot] = bfpack(h0, h1);
            sm.alp[nxt][akc][pr][aslot] = bfpack(pref.x - h0, pref.y - h1);
        }
        __syncthreads();
    }
}

// ---------------------------------------------------------------------------
// Kernel 2: heads, single-pass tf32, 64-row tiles, 256 threads, 2 CTAs/SM.
// Smem = 114688 B exactly. 4096 CTAs.
// ---------------------------------------------------------------------------
struct HeadSmem {
    float Xp[8][64][8];     // packed state tile          16384 B
    float WA[16384];        // L1 W [8][256][8]; then W2 halves [16][128][8]  65536 B
    float A1p[16][64][8];   // packed relu(layer1)        32768 B
};

__global__ void __launch_bounds__(256, 2)
heads_kernel(const float* __restrict__ states,
             const float* __restrict__ dec_w1, const float* __restrict__ dec_b1,
             const float* __restrict__ dec_w2, const float* __restrict__ dec_b2,
             const float* __restrict__ rew_w1, const float* __restrict__ rew_b1,
             const float* __restrict__ rew_w2, const float* __restrict__ rew_b2,
             const float* __restrict__ saf_w1, const float* __restrict__ saf_b1,
             const float* __restrict__ saf_w2, const float* __restrict__ saf_b2,
             float* __restrict__ obs, float* __restrict__ rew,
             float* __restrict__ saf) {
    extern __shared__ char smem_raw[];
    HeadSmem& sm = *reinterpret_cast<HeadSmem*>(smem_raw);
    const int tid = threadIdx.x;
    const int m0 = blockIdx.x * 64;

    // ---- prologue staging ----
    for (int i = tid; i < 64 * 16; i += 256) {
        const int r = i >> 4, c4 = (i & 15) * 4;
        const int m = m0 + r, b = m >> 7, t = m & 127;
        const float4 v = *reinterpret_cast<const float4*>(
            &states[((long)b * (TT + 1) + t + 1) * SS + c4]);
        float* p = &sm.Xp[c4 >> 3][r][0];
        if ((c4 & 4) == 0) {
            p[0] = tf32r(v.x); p[2] = tf32r(v.y); p[4] = tf32r(v.z); p[6] = tf32r(v.w);
        } else {
            p[1] = tf32r(v.x); p[3] = tf32r(v.y); p[5] = tf32r(v.z); p[7] = tf32r(v.w);
        }
    }
    for (int i = tid; i < 256 * 64; i += 256) {
        const int n = i >> 6, k = i & 63;
        float wv;
        if (n < 128)      wv = dec_w1[n * 64 + k];
        else if (n < 192) wv = rew_w1[(n - 128) * 64 + k];
        else              wv = saf_w1[(n - 192) * 64 + k];
        sm.WA[(k >> 3) * 2048 + n * 8 + pidx(k & 7)] = tf32r(wv);
    }
    __syncthreads();

    const int lane = tid & 31;
    const int w = tid >> 5;
    const int wr = w & 1;          // row half (32 rows)
    const int wc = w >> 1;         // col quarter (64 cols of L1)
    const int gid = lane >> 2;
    const int t4 = lane & 3;
    const int i0p = pidx(t4 * 2);
    const int i1p = pidx(t4 * 2 + 1);

    // ---- Layer 1: (64x64) @ (64x256) ----
    float acc[2][8][4];
    #pragma unroll
    for (int mt = 0; mt < 2; ++mt)
        #pragma unroll
        for (int nt = 0; nt < 8; ++nt)
            #pragma unroll
            for (int q = 0; q < 4; ++q) acc[mt][nt][q] = 0.f;

    #pragma unroll
    for (int ks = 0; ks < 8; ++ks) {
        uint32_t a[2][4];
        #pragma unroll
        for (int mt = 0; mt < 2; ++mt) {
            const int R = wr * 32 + mt * 16;
            const float2 f0 = *reinterpret_cast<const float2*>(&sm.Xp[ks][R + gid][2 * t4]);
            const float2 f1 = *reinterpret_cast<const float2*>(&sm.Xp[ks][R + gid + 8][2 * t4]);
            a[mt][0] = __float_as_uint(f0.x); a[mt][1] = __float_as_uint(f1.x);
            a[mt][2] = __float_as_uint(f0.y); a[mt][3] = __float_as_uint(f1.y);
        }
        #pragma unroll
        for (int nt = 0; nt < 8; ++nt) {
            const int n0 = wc * 64 + nt * 8;
            const float2 bv = *reinterpret_cast<const float2*>(
                &sm.WA[ks * 2048 + (n0 + gid) * 8 + 2 * t4]);
            mma_tf32(acc[0][nt], a[0], __float_as_uint(bv.x), __float_as_uint(bv.y));
            mma_tf32(acc[1][nt], a[1], __float_as_uint(bv.x), __float_as_uint(bv.y));
        }
    }

    if (wc < 2) {
        #pragma unroll
        for (int mt = 0; mt < 2; ++mt) {
            const int R = wr * 32 + mt * 16;
            #pragma unroll
            for (int nt = 0; nt < 8; ++nt) {
                const int ks2 = wc * 8 + nt;
                const int col = wc * 64 + nt * 8 + t4 * 2;
                const float bA  = __ldg(&dec_b1[col]);
                const float bBv = __ldg(&dec_b1[col + 1]);
                sm.A1p[ks2][R + gid][i0p]     = tf32r(fmaxf(acc[mt][nt][0] + bA, 0.f));
                sm.A1p[ks2][R + gid][i1p]     = tf32r(fmaxf(acc[mt][nt][1] + bBv, 0.f));
                sm.A1p[ks2][R + gid + 8][i0p] = tf32r(fmaxf(acc[mt][nt][2] + bA, 0.f));
                sm.A1p[ks2][R + gid + 8][i1p] = tf32r(fmaxf(acc[mt][nt][3] + bBv, 0.f));
            }
        }
    } else {
        const bool is_rew = (wc == 2);
        const float* w1b = is_rew ? rew_b1 : saf_b1;
        const float* w2v = is_rew ? rew_w2 : saf_w2;
        const float bias2 = is_rew ? __ldg(&rew_b2[0]) : __ldg(&saf_b2[0]);
        float* outp = is_rew ? rew : saf;
        #pragma unroll
        for (int mt = 0; mt < 2; ++mt) {
            float p0 = 0.f, p1 = 0.f;
            #pragma unroll
            for (int nt = 0; nt < 8; ++nt) {
                const int l = nt * 8 + t4 * 2;
                const float bA  = __ldg(&w1b[l]);
                const float bBv = __ldg(&w1b[l + 1]);
                const float v00 = fmaxf(acc[mt][nt][0] + bA, 0.f);
                const float v01 = fmaxf(acc[mt][nt][1] + bBv, 0.f);
                const float v10 = fmaxf(acc[mt][nt][2] + bA, 0.f);
                const float v11 = fmaxf(acc[mt][nt][3] + bBv, 0.f);
                const float wl0 = __ldg(&w2v[l]);
                const float wl1 = __ldg(&w2v[l + 1]);
                p0 = fmaf(v00, wl0, fmaf(v01, wl1, p0));
                p1 = fmaf(v10, wl0, fmaf(v11, wl1, p1));
            }
            p0 += __shfl_xor_sync(0xFFFFFFFFu, p0, 1);
            p0 += __shfl_xor_sync(0xFFFFFFFFu, p0, 2);
            p1 += __shfl_xor_sync(0xFFFFFFFFu, p1, 1);
            p1 += __shfl_xor_sync(0xFFFFFFFFu, p1, 2);
            if (t4 == 0) {
                const int R = wr * 32 + mt * 16;
                outp[m0 + R + gid]     = p0 + bias2;
                outp[m0 + R + gid + 8] = p1 + bias2;
            }
        }
    }
    __syncthreads();

    // ---- Layer 2: obs = A1(64x128) @ dec_w2^T, two N-halves of 128 ----
    for (int half = 0; half < 2; ++half) {
        for (int i = tid; i < 128 * 128; i += 256) {
            const int n = i >> 7, k = i & 127;
            sm.WA[(k >> 3) * 1024 + n * 8 + pidx(k & 7)] =
                tf32r(dec_w2[(half * 128 + n) * 128 + k]);
        }
        __syncthreads();

        float acc2[2][4][4];
        #pragma unroll
        for (int mt = 0; mt < 2; ++mt)
            #pragma unroll
            for (int nt = 0; nt < 4; ++nt)
                #pragma unroll
                for (int q = 0; q < 4; ++q) acc2[mt][nt][q] = 0.f;

        #pragma unroll
        for (int ks = 0; ks < 16; ++ks) {
            uint32_t a[2][4];
            #pragma unroll
            for (int mt = 0; mt < 2; ++mt) {
                const int R = wr * 32 + mt * 16;
                const float2 f0 = *reinterpret_cast<const float2*>(&sm.A1p[ks][R + gid][2 * t4]);
                const float2 f1 = *reinterpret_cast<const float2*>(&sm.A1p[ks][R + gid + 8][2 * t4]);
                a[mt][0] = __float_as_uint(f0.x); a[mt][1] = __float_as_uint(f1.x);
                a[mt][2] = __float_as_uint(f0.y); a[mt][3] = __float_as_uint(f1.y);
            }
            #pragma unroll
            for (int nt = 0; nt < 4; ++nt) {
                const int n0 = wc * 32 + nt * 8;
                const float2 bv = *reinterpret_cast<const float2*>(
                    &sm.WA[ks * 1024 + (n0 + gid) * 8 + 2 * t4]);
                mma_tf32(acc2[0][nt], a[0], __float_as_uint(bv.x), __float_as_uint(bv.y));
                mma_tf32(acc2[1][nt], a[1], __float_as_uint(bv.x), __float_as_uint(bv.y));
            }
        }

        #pragma unroll
        for (int mt = 0; mt < 2; ++mt) {
            const int R = wr * 32 + mt * 16;
            #pragma unroll
            for (int nt = 0; nt < 4; ++nt) {
                const int cg = half * 128 + wc * 32 + nt * 8 + t4 * 2;
                const float2 b2v = *reinterpret_cast<const float2*>(&dec_b2[cg]);
                *reinterpret_cast<float2*>(&obs[(long)(m0 + R + gid) * OO + cg]) =
                    make_float2(acc2[mt][nt][0] + b2v.x, acc2[mt][nt][1] + b2v.y);
                *reinterpret_cast<float2*>(&obs[(long)(m0 + R + gid + 8) * OO + cg]) =
                    make_float2(acc2[mt][nt][2] + b2v.x, acc2[mt][nt][3] + b2v.y);
            }
        }
        __syncthreads();
    }
}

// ---------------------------------------------------------------------------
extern "C" void kernel_launch(void* const* d_in, const int* in_sizes, int n_in,
                              void* d_out, int out_size) {
    const float* initial_state = (const float*)d_in[0];
    const float* actions = (const float*)d_in[1];
    const float* W_ih = (const float*)d_in[2];
    const float* W_hh = (const float*)d_in[3];
    const float* b_ih = (const float*)d_in[4];
    const float* b_hh = (const float*)d_in[5];
    const float* dec_w1 = (const float*)d_in[6];
    const float* dec_b1 = (const float*)d_in[7];
    const float* dec_w2 = (const float*)d_in[8];
    const float* dec_b2 = (const float*)d_in[9];
    const float* rew_w1 = (const float*)d_in[10];
    const float* rew_b1 = (const float*)d_in[11];
    const float* rew_w2 = (const float*)d_in[12];
    const float* rew_b2 = (const float*)d_in[13];
    const float* saf_w1 = (const float*)d_in[14];
    const float* saf_b1 = (const float*)d_in[15];
    const float* saf_w2 = (const float*)d_in[16];
    const float* saf_b2 = (const float*)d_in[17];

    float* out = (float*)d_out;
    float* states = out;
    float* obs = out + (long)BB * (TT + 1) * SS;
    float* rew = obs + (long)BB * TT * OO;
    float* saf = rew + (long)BB * TT;

    cudaFuncSetAttribute(scan_kernel, cudaFuncAttributeMaxDynamicSharedMemorySize,
                         (int)sizeof(ScanSmem));
    cudaFuncSetAttribute(heads_kernel, cudaFuncAttributeMaxDynamicSharedMemorySize,
                         (int)sizeof(HeadSmem));

    scan_kernel<<<BB / 16, 256, sizeof(ScanSmem)>>>(
        initial_state, actions, W_ih, W_hh, b_ih, b_hh, states);
    heads_kernel<<<(BB * TT) / 64, 256, sizeof(HeadSmem)>>>(
        states, dec_w1, dec_b1, dec_w2, dec_b2,
        rew_w1, rew_b1, rew_w2, rew_b2,
        saf_w1, saf_b1, saf_w2, saf_b2,
        obs, rew, saf);
}

// round 9
// speedup vs baseline: 2.5896x; 1.2165x over previous
#include <cuda_runtime.h>
#include <cuda_bf16.h>
#include <cstdint>
#include <math.h>

#define BB 2048
#define TT 128
#define SS 64
#define AA 32
#define G3 192
#define HH 128
#define OO 256

#define DEV __device__ __forceinline__

DEV uint32_t tf32b(float x) {
    uint32_t u;
    asm("cvt.rna.tf32.f32 %0, %1;" : "=r"(u) : "f"(x));
    return u;
}
DEV float tf32r(float x) { return __uint_as_float(tf32b(x)); }

// packed pair index: element u (0..7) of an 8-group -> slot in float2-pair array
DEV int pidx(int u) { return (u < 4) ? (u << 1) : (((u - 4) << 1) | 1); }

DEV float bfhi(float x) { return __bfloat162float(__float2bfloat16_rn(x)); }
DEV uint32_t bfpack(float x, float y) {
    __nv_bfloat162 t = __floats2bfloat162_rn(x, y);
    return *reinterpret_cast<uint32_t*>(&t);
}

DEV void cp_async4(uint32_t smem_addr, const void* gptr) {
    asm volatile("cp.async.ca.shared.global [%0], [%1], 4;"
                 :: "r"(smem_addr), "l"(gptr));
}

DEV void mma_tf32(float* d, const uint32_t* a, uint32_t b0, uint32_t b1) {
    asm volatile(
        "mma.sync.aligned.m16n8k8.row.col.f32.tf32.tf32.f32 "
        "{%0,%1,%2,%3}, {%4,%5,%6,%7}, {%8,%9}, {%0,%1,%2,%3};"
        : "+f"(d[0]), "+f"(d[1]), "+f"(d[2]), "+f"(d[3])
        : "r"(a[0]), "r"(a[1]), "r"(a[2]), "r"(a[3]), "r"(b0), "r"(b1));
}

DEV void mma_bf16(float* d, const uint32_t* a, uint32_t b0, uint32_t b1) {
    asm volatile(
        "mma.sync.aligned.m16n8k16.row.col.f32.bf16.bf16.f32 "
        "{%0,%1,%2,%3}, {%4,%5,%6,%7}, {%8,%9}, {%0,%1,%2,%3};"
        : "+f"(d[0]), "+f"(d[1]), "+f"(d[2]), "+f"(d[3])
        : "r"(a[0]), "r"(a[1]), "r"(a[2]), "r"(a[3]), "r"(b0), "r"(b1));
}

// ---------------------------------------------------------------------------
// Kernel 1: GRU scan, bf16x3 mma.m16n8k16. 128 CTAs x 16 rows, 256 threads.
// (unchanged from round 8 — measured ~192 us)
// ---------------------------------------------------------------------------
struct ScanSmem {
    uint32_t hhp[2][4][16][8];
    uint32_t hlp[2][4][16][8];
    uint32_t ahp[2][2][16][8];
    uint32_t alp[2][2][16][8];
    uint32_t loIp[6][192][8];
    uint32_t loHp[4][192][8];
};

__global__ void __launch_bounds__(256, 1)
scan_kernel(const float* __restrict__ initial_state,
            const float* __restrict__ actions,
            const float* __restrict__ W_ih,
            const float* __restrict__ W_hh,
            const float* __restrict__ b_ih,
            const float* __restrict__ b_hh,
            float* __restrict__ states) {
    extern __shared__ char smem_raw[];
    ScanSmem& sm = *reinterpret_cast<ScanSmem*>(smem_raw);
    const int tid = threadIdx.x;
    const int w = tid >> 5;
    const int lane = tid & 31;
    const int gid = lane >> 2;
    const int t4 = lane & 3;
    const int b0 = blockIdx.x * 16;

    for (int i = tid; i < 192 * 48; i += 256) {
        const int n = i / 48, p = i % 48;
        const float v0 = W_ih[n * 96 + 2 * p];
        const float v1 = W_ih[n * 96 + 2 * p + 1];
        sm.loIp[p >> 3][n][pidx(p & 7)] = bfpack(v0 - bfhi(v0), v1 - bfhi(v1));
    }
    for (int i = tid; i < 192 * 32; i += 256) {
        const int n = i / 32, p = i % 32;
        const float v0 = W_hh[n * 64 + 2 * p];
        const float v1 = W_hh[n * 64 + 2 * p + 1];
        sm.loHp[p >> 3][n][pidx(p & 7)] = bfpack(v0 - bfhi(v0), v1 - bfhi(v1));
    }

    uint32_t BI[3][6][2], BH[3][4][2];
    #pragma unroll
    for (int ti = 0; ti < 3; ++ti) {
        const int n = w * 8 + ti * 64 + gid;
        #pragma unroll
        for (int kc = 0; kc < 6; ++kc) {
            const int k0 = kc * 16 + 2 * t4;
            BI[ti][kc][0] = bfpack(bfhi(W_ih[n * 96 + k0]),     bfhi(W_ih[n * 96 + k0 + 1]));
            BI[ti][kc][1] = bfpack(bfhi(W_ih[n * 96 + k0 + 8]), bfhi(W_ih[n * 96 + k0 + 9]));
        }
        #pragma unroll
        for (int kc = 0; kc < 4; ++kc) {
            const int k0 = kc * 16 + 2 * t4;
            BH[ti][kc][0] = bfpack(bfhi(W_hh[n * 64 + k0]),     bfhi(W_hh[n * 64 + k0 + 1]));
            BH[ti][kc][1] = bfpack(bfhi(W_hh[n * 64 + k0 + 8]), bfhi(W_hh[n * 64 + k0 + 9]));
        }
    }

    const int c = w * 8 + t4 * 2;
    const float br_[2]  = {b_ih[c] + b_hh[c],           b_ih[c + 1] + b_hh[c + 1]};
    const float bz_[2]  = {b_ih[64 + c] + b_hh[64 + c], b_ih[65 + c] + b_hh[65 + c]};
    const float biN_[2] = {b_ih[128 + c], b_ih[129 + c]};
    const float bhN_[2] = {b_hh[128 + c], b_hh[129 + c]};

    for (int i = tid; i < 16 * 32; i += 256) {
        const int r = i >> 5, p = i & 31;
        const float v0 = initial_state[(long)(b0 + r) * SS + 2 * p];
        const float v1 = initial_state[(long)(b0 + r) * SS + 2 * p + 1];
        states[(long)(b0 + r) * ((TT + 1) * SS) + 2 * p]     = v0;
        states[(long)(b0 + r) * ((TT + 1) * SS) + 2 * p + 1] = v1;
        const float h0 = bfhi(v0), h1 = bfhi(v1);
        sm.hhp[0][p >> 3][r][pidx(p & 7)] = bfpack(h0, h1);
        sm.hlp[0][p >> 3][r][pidx(p & 7)] = bfpack(v0 - h0, v1 - h1);
    }
    float hreg[4];
    hreg[0] = initial_state[(long)(b0 + gid) * SS + c];
    hreg[1] = initial_state[(long)(b0 + gid) * SS + c + 1];
    hreg[2] = initial_state[(long)(b0 + gid + 8) * SS + c];
    hreg[3] = initial_state[(long)(b0 + gid + 8) * SS + c + 1];

    const int pr = tid >> 4;
    const int pp = tid & 15;
    const int akc = pp >> 3, aslot = pidx(pp & 7);
    {
        const float2 v = *reinterpret_cast<const float2*>(
            &actions[((long)(b0 + pr) * TT) * AA + 2 * pp]);
        const float h0 = bfhi(v.x), h1 = bfhi(v.y);
        sm.ahp[0][akc][pr][aslot] = bfpack(h0, h1);
        sm.alp[0][akc][pr][aslot] = bfpack(v.x - h0, v.y - h1);
    }
    __syncthreads();

    const int hkc   = (w * 4 + t4) >> 3;
    const int hslot = pidx((w * 4 + t4) & 7);

    for (int t = 0; t < TT; ++t) {
        const int cur = t & 1, nxt = cur ^ 1;
        const bool dopref = (t + 1 < TT);
        float2 pref = make_float2(0.f, 0.f);
        if (dopref)
            pref = *reinterpret_cast<const float2*>(
                &actions[((long)(b0 + pr) * TT + (t + 1)) * AA + 2 * pp]);

        float aR[4]  = {0.f, 0.f, 0.f, 0.f};
        float aZ[4]  = {0.f, 0.f, 0.f, 0.f};
        float aNI[4] = {0.f, 0.f, 0.f, 0.f};
        float aNH[4] = {0.f, 0.f, 0.f, 0.f};

        #pragma unroll
        for (int kc = 0; kc < 6; ++kc) {
            uint2 h0, h1, l0, l1;
            if (kc < 4) {
                h0 = *reinterpret_cast<const uint2*>(&sm.hhp[cur][kc][gid][2 * t4]);
                h1 = *reinterpret_cast<const uint2*>(&sm.hhp[cur][kc][gid + 8][2 * t4]);
                l0 = *reinterpret_cast<const uint2*>(&sm.hlp[cur][kc][gid][2 * t4]);
                l1 = *reinterpret_cast<const uint2*>(&sm.hlp[cur][kc][gid + 8][2 * t4]);
            } else {
                h0 = *reinterpret_cast<const uint2*>(&sm.ahp[cur][kc - 4][gid][2 * t4]);
                h1 = *reinterpret_cast<const uint2*>(&sm.ahp[cur][kc - 4][gid + 8][2 * t4]);
                l0 = *reinterpret_cast<const uint2*>(&sm.alp[cur][kc - 4][gid][2 * t4]);
                l1 = *reinterpret_cast<const uint2*>(&sm.alp[cur][kc - 4][gid + 8][2 * t4]);
            }
            const uint32_t ah[4] = {h0.x, h1.x, h0.y, h1.y};
            const uint32_t al[4] = {l0.x, l1.x, l0.y, l1.y};

            #pragma unroll
            for (int ti = 0; ti < 3; ++ti) {
                float* acc = (ti == 0) ? aR : (ti == 1) ? aZ : aNI;
                const int n = w * 8 + ti * 64 + gid;
                const uint2 bl = *reinterpret_cast<const uint2*>(&sm.loIp[kc][n][2 * t4]);
                mma_bf16(acc, ah, BI[ti][kc][0], BI[ti][kc][1]);
                mma_bf16(acc, al, BI[ti][kc][0], BI[ti][kc][1]);
                mma_bf16(acc, ah, bl.x, bl.y);
            }
            if (kc < 4) {
                #pragma unroll
                for (int ti = 0; ti < 3; ++ti) {
                    float* acc = (ti == 0) ? aR : (ti == 1) ? aZ : aNH;
                    const int n = w * 8 + ti * 64 + gid;
                    const uint2 bl = *reinterpret_cast<const uint2*>(&sm.loHp[kc][n][2 * t4]);
                    mma_bf16(acc, ah, BH[ti][kc][0], BH[ti][kc][1]);
                    mma_bf16(acc, al, BH[ti][kc][0], BH[ti][kc][1]);
                    mma_bf16(acc, ah, bl.x, bl.y);
                }
            }
        }

        #pragma unroll
        for (int v = 0; v < 4; ++v) {
            const int p = v & 1;
            const float sr = aR[v] + br_[p];
            const float sz = aZ[v] + bz_[p];
            const float rg = __fdividef(1.f, 1.f + __expf(-sr));
            const float zg = __fdividef(1.f, 1.f + __expf(-sz));
            const float narg = aNI[v] + biN_[p] + rg * (aNH[v] + bhN_[p]);
            const float e2 = __expf(2.f * narg);
            const float ng = 1.f - __fdividef(2.f, e2 + 1.f);
            hreg[v] = (1.f - zg) * ng + zg * hreg[v];
        }

        {
            const float hi0 = bfhi(hreg[0]), hi1 = bfhi(hreg[1]);
            const float hi2 = bfhi(hreg[2]), hi3 = bfhi(hreg[3]);
            sm.hhp[nxt][hkc][gid][hslot]     = bfpack(hi0, hi1);
            sm.hhp[nxt][hkc][gid + 8][hslot] = bfpack(hi2, hi3);
            sm.hlp[nxt][hkc][gid][hslot]     = bfpack(hreg[0] - hi0, hreg[1] - hi1);
            sm.hlp[nxt][hkc][gid + 8][hslot] = bfpack(hreg[2] - hi2, hreg[3] - hi3);
        }
        *reinterpret_cast<float2*>(
            &states[((long)(b0 + gid) * (TT + 1) + t + 1) * SS + c]) =
            make_float2(hreg[0], hreg[1]);
        *reinterpret_cast<float2*>(
            &states[((long)(b0 + gid + 8) * (TT + 1) + t + 1) * SS + c]) =
            make_float2(hreg[2], hreg[3]);
        if (dopref) {
            const float h0 = bfhi(pref.x), h1 = bfhi(pref.y);
            sm.ahp[nxt][akc][pr][aslot] = bfpack(h0, h1);
            sm.alp[nxt][akc][pr][aslot] = bfpack(pref.x - h0, pref.y - h1);
        }
        __syncthreads();
    }
}

// ---------------------------------------------------------------------------
// Kernel 2: heads, round-7 shape (128-row, 512 thr) + cp.async for W2 half1.
// ---------------------------------------------------------------------------
struct HeadSmem {
    float Xp[8][128][8];    // 32768 B
    float WA[16384];        // L1 weights [8][256][8]; later W2 half1 [16][128][8]
    float A1p[16][128][8];  // 65536 B
    float WB[16][128][8];   // W2 half0 (prefetched) 65536 B
    float b1s[256];
    float w2r[64];
    float w2s[64];
};

__global__ void __launch_bounds__(512, 1)
heads_kernel(const float* __restrict__ states,
             const float* __restrict__ dec_w1, const float* __restrict__ dec_b1,
             const float* __restrict__ dec_w2, const float* __restrict__ dec_b2,
             const float* __restrict__ rew_w1, const float* __restrict__ rew_b1,
             const float* __restrict__ rew_w2, const float* __restrict__ rew_b2,
             const float* __restrict__ saf_w1, const float* __restrict__ saf_b1,
             const float* __restrict__ saf_w2, const float* __restrict__ saf_b2,
             float* __restrict__ obs, float* __restrict__ rew,
             float* __restrict__ saf) {
    extern __shared__ char smem_raw[];
    HeadSmem& sm = *reinterpret_cast<HeadSmem*>(smem_raw);
    const int tid = threadIdx.x;
    const int m0 = blockIdx.x * 128;

    // ---- prologue staging ----
    for (int i = tid; i < 128 * 16; i += 512) {
        const int r = i >> 4, c4 = (i & 15) * 4;
        const int m = m0 + r, b = m >> 7, t = m & 127;
        const float4 v = *reinterpret_cast<const float4*>(
            &states[((long)b * (TT + 1) + t + 1) * SS + c4]);
        float* p = &sm.Xp[c4 >> 3][r][0];
        if ((c4 & 4) == 0) {
            p[0] = tf32r(v.x); p[2] = tf32r(v.y); p[4] = tf32r(v.z); p[6] = tf32r(v.w);
        } else {
            p[1] = tf32r(v.x); p[3] = tf32r(v.y); p[5] = tf32r(v.z); p[7] = tf32r(v.w);
        }
    }
    for (int i = tid; i < 256 * 64; i += 512) {
        const int n = i >> 6, k = i & 63;
        float wv;
        if (n < 128)      wv = dec_w1[n * 64 + k];
        else if (n < 192) wv = rew_w1[(n - 128) * 64 + k];
        else              wv = saf_w1[(n - 192) * 64 + k];
        sm.WA[(k >> 3) * 2048 + n * 8 + pidx(k & 7)] = tf32r(wv);
    }
    for (int i = tid; i < 128 * 128; i += 512) {   // W2 half0 prefetch
        const int n = i >> 7, k = i & 127;
        sm.WB[k >> 3][n][pidx(k & 7)] = tf32r(dec_w2[n * 128 + k]);
    }
    for (int i = tid; i < 256; i += 512)
        sm.b1s[i] = (i < 128) ? dec_b1[i] : ((i < 192) ? rew_b1[i - 128] : saf_b1[i - 192]);
    for (int i = tid; i < 64; i += 512) { sm.w2r[i] = rew_w2[i]; sm.w2s[i] = saf_w2[i]; }
    __syncthreads();

    const int lane = tid & 31;
    const int w = tid >> 5;
    const int wr = w & 3;
    const int wc = w >> 2;
    const int gid = lane >> 2;
    const int t4 = lane & 3;
    const int i0p = pidx(t4 * 2);
    const int i1p = pidx(t4 * 2 + 1);

    // ---- Layer 1: (128x64) @ (64x256) ----
    float acc[2][8][4];
    #pragma unroll
    for (int mt = 0; mt < 2; ++mt)
        #pragma unroll
        for (int nt = 0; nt < 8; ++nt)
            #pragma unroll
            for (int q = 0; q < 4; ++q) acc[mt][nt][q] = 0.f;

    #pragma unroll
    for (int ks = 0; ks < 8; ++ks) {
        uint32_t a[2][4];
        #pragma unroll
        for (int mt = 0; mt < 2; ++mt) {
            const int R = wr * 32 + mt * 16;
            const float2 f0 = *reinterpret_cast<const float2*>(&sm.Xp[ks][R + gid][2 * t4]);
            const float2 f1 = *reinterpret_cast<const float2*>(&sm.Xp[ks][R + gid + 8][2 * t4]);
            a[mt][0] = __float_as_uint(f0.x); a[mt][1] = __float_as_uint(f1.x);
            a[mt][2] = __float_as_uint(f0.y); a[mt][3] = __float_as_uint(f1.y);
        }
        #pragma unroll
        for (int nt = 0; nt < 8; ++nt) {
            const int n0 = wc * 64 + nt * 8;
            const float2 bv = *reinterpret_cast<const float2*>(
                &sm.WA[ks * 2048 + (n0 + gid) * 8 + 2 * t4]);
            mma_tf32(acc[0][nt], a[0], __float_as_uint(bv.x), __float_as_uint(bv.y));
            mma_tf32(acc[1][nt], a[1], __float_as_uint(bv.x), __float_as_uint(bv.y));
        }
    }

    if (wc < 2) {
        #pragma unroll
        for (int mt = 0; mt < 2; ++mt) {
            const int R = wr * 32 + mt * 16;
            #pragma unroll
            for (int nt = 0; nt < 8; ++nt) {
                const int ks2 = wc * 8 + nt;
                const int col = wc * 64 + nt * 8 + t4 * 2;
                const float bA = sm.b1s[col], bBv = sm.b1s[col + 1];
                sm.A1p[ks2][R + gid][i0p]     = tf32r(fmaxf(acc[mt][nt][0] + bA, 0.f));
                sm.A1p[ks2][R + gid][i1p]     = tf32r(fmaxf(acc[mt][nt][1] + bBv, 0.f));
                sm.A1p[ks2][R + gid + 8][i0p] = tf32r(fmaxf(acc[mt][nt][2] + bA, 0.f));
                sm.A1p[ks2][R + gid + 8][i1p] = tf32r(fmaxf(acc[mt][nt][3] + bBv, 0.f));
            }
        }
    } else {
        const bool is_rew = (wc == 2);
        const float* w2v = is_rew ? sm.w2r : sm.w2s;
        const int bbase = is_rew ? 128 : 192;
        const float bias2 = is_rew ? rew_b2[0] : saf_b2[0];
        float* outp = is_rew ? rew : saf;
        #pragma unroll
        for (int mt = 0; mt < 2; ++mt) {
            float p0 = 0.f, p1 = 0.f;
            #pragma unroll
            for (int nt = 0; nt < 8; ++nt) {
                const int l = nt * 8 + t4 * 2;
                const float bA = sm.b1s[bbase + l], bBv = sm.b1s[bbase + l + 1];
                const float v00 = fmaxf(acc[mt][nt][0] + bA, 0.f);
                const float v01 = fmaxf(acc[mt][nt][1] + bBv, 0.f);
                const float v10 = fmaxf(acc[mt][nt][2] + bA, 0.f);
                const float v11 = fmaxf(acc[mt][nt][3] + bBv, 0.f);
                p0 = fmaf(v00, w2v[l], fmaf(v01, w2v[l + 1], p0));
                p1 = fmaf(v10, w2v[l], fmaf(v11, w2v[l + 1], p1));
            }
            p0 += __shfl_xor_sync(0xFFFFFFFFu, p0, 1);
            p0 += __shfl_xor_sync(0xFFFFFFFFu, p0, 2);
            p1 += __shfl_xor_sync(0xFFFFFFFFu, p1, 1);
            p1 += __shfl_xor_sync(0xFFFFFFFFu, p1, 2);
            if (t4 == 0) {
                const int R = wr * 32 + mt * 16;
                outp[m0 + R + gid]     = p0 + bias2;
                outp[m0 + R + gid + 8] = p1 + bias2;
            }
        }
    }
    __syncthreads();

    // ---- async-stage W2 half1 into WA (dead after L1); overlaps half0 compute
    {
        const uint32_t wa0 = (uint32_t)__cvta_generic_to_shared(&sm.WA[0]);
        for (int i = tid; i < 128 * 128; i += 512) {
            const int n = i >> 7, k = i & 127;
            cp_async4(wa0 + 4u * ((k >> 3) * 1024 + n * 8 + pidx(k & 7)),
                      &dec_w2[(128 + n) * 128 + k]);
        }
        asm volatile("cp.async.commit_group;");
    }

    // ---- Layer 2 half 0 (weights already in WB) ----
    {
        float acc2[2][4][4];
        #pragma unroll
        for (int mt = 0; mt < 2; ++mt)
            #pragma unroll
            for (int nt = 0; nt < 4; ++nt)
                #pragma unroll
                for (int q = 0; q < 4; ++q) acc2[mt][nt][q] = 0.f;

        #pragma unroll
        for (int ks = 0; ks < 16; ++ks) {
            uint32_t a[2][4];
            #pragma unroll
            for (int mt = 0; mt < 2; ++mt) {
                const int R = wr * 32 + mt * 16;
                const float2 f0 = *reinterpret_cast<const float2*>(&sm.A1p[ks][R + gid][2 * t4]);
                const float2 f1 = *reinterpret_cast<const float2*>(&sm.A1p[ks][R + gid + 8][2 * t4]);
                a[mt][0] = __float_as_uint(f0.x); a[mt][1] = __float_as_uint(f1.x);
                a[mt][2] = __float_as_uint(f0.y); a[mt][3] = __float_as_uint(f1.y);
            }
            #pragma unroll
            for (int nt = 0; nt < 4; ++nt) {
                const int n0 = wc * 32 + nt * 8;
                const float2 bv = *reinterpret_cast<const float2*>(&sm.WB[ks][n0 + gid][2 * t4]);
                mma_tf32(acc2[0][nt], a[0], __float_as_uint(bv.x), __float_as_uint(bv.y));
                mma_tf32(acc2[1][nt], a[1], __float_as_uint(bv.x), __float_as_uint(bv.y));
            }
        }
        #pragma unroll
        for (int mt = 0; mt < 2; ++mt) {
            const int R = wr * 32 + mt * 16;
            #pragma unroll
            for (int nt = 0; nt < 4; ++nt) {
                const int cg = wc * 32 + nt * 8 + t4 * 2;
                const float2 b2v = *reinterpret_cast<const float2*>(&dec_b2[cg]);
                *reinterpret_cast<float2*>(&obs[(long)(m0 + R + gid) * OO + cg]) =
                    make_float2(acc2[mt][nt][0] + b2v.x, acc2[mt][nt][1] + b2v.y);
                *reinterpret_cast<float2*>(&obs[(long)(m0 + R + gid + 8) * OO + cg]) =
                    make_float2(acc2[mt][nt][2] + b2v.x, acc2[mt][nt][3] + b2v.y);
            }
        }
    }

    asm volatile("cp.async.wait_group 0;" ::: "memory");
    __syncthreads();

    // ---- Layer 2 half 1 (weights in WA, raw fp32 -> mma-truncated tf32) ----
    {
        float acc2[2][4][4];
        #pragma unroll
        for (int mt = 0; mt < 2; ++mt)
            #pragma unroll
            for (int nt = 0; nt < 4; ++nt)
                #pragma unroll
                for (int q = 0; q < 4; ++q) acc2[mt][nt][q] = 0.f;

        #pragma unroll
        for (int ks = 0; ks < 16; ++ks) {
            uint32_t a[2][4];
            #pragma unroll
            for (int mt = 0; mt < 2; ++mt) {
                const int R = wr * 32 + mt * 16;
                const float2 f0 = *reinterpret_cast<const float2*>(&sm.A1p[ks][R + gid][2 * t4]);
                const float2 f1 = *reinterpret_cast<const float2*>(&sm.A1p[ks][R + gid + 8][2 * t4]);
                a[mt][0] = __float_as_uint(f0.x); a[mt][1] = __float_as_uint(f1.x);
                a[mt][2] = __float_as_uint(f0.y); a[mt][3] = __float_as_uint(f1.y);
            }
            #pragma unroll
            for (int nt = 0; nt < 4; ++nt) {
                const int n0 = wc * 32 + nt * 8;
                const float2 bv = *reinterpret_cast<const float2*>(
                    &sm.WA[ks * 1024 + (n0 + gid) * 8 + 2 * t4]);
                mma_tf32(acc2[0][nt], a[0], __float_as_uint(bv.x), __float_as_uint(bv.y));
                mma_tf32(acc2[1][nt], a[1], __float_as_uint(bv.x), __float_as_uint(bv.y));
            }
        }
        #pragma unroll
        for (int mt = 0; mt < 2; ++mt) {
            const int R = wr * 32 + mt * 16;
            #pragma unroll
            for (int nt = 0; nt < 4; ++nt) {
                const int cg = 128 + wc * 32 + nt * 8 + t4 * 2;
                const float2 b2v = *reinterpret_cast<const float2*>(&dec_b2[cg]);
                *reinterpret_cast<float2*>(&obs[(long)(m0 + R + gid) * OO + cg]) =
                    make_float2(acc2[mt][nt][0] + b2v.x, acc2[mt][nt][1] + b2v.y);
                *reinterpret_cast<float2*>(&obs[(long)(m0 + R + gid + 8) * OO + cg]) =
                    make_float2(acc2[mt][nt][2] + b2v.x, acc2[mt][nt][3] + b2v.y);
            }
        }
    }
}

// ---------------------------------------------------------------------------
extern "C" void kernel_launch(void* const* d_in, const int* in_sizes, int n_in,
                              void* d_out, int out_size) {
    const float* initial_state = (const float*)d_in[0];
    const float* actions = (const float*)d_in[1];
    const float* W_ih = (const float*)d_in[2];
    const float* W_hh = (const float*)d_in[3];
    const float* b_ih = (const float*)d_in[4];
    const float* b_hh = (const float*)d_in[5];
    const float* dec_w1 = (const float*)d_in[6];
    const float* dec_b1 = (const float*)d_in[7];
    const float* dec_w2 = (const float*)d_in[8];
    const float* dec_b2 = (const float*)d_in[9];
    const float* rew_w1 = (const float*)d_in[10];
    const float* rew_b1 = (const float*)d_in[11];
    const float* rew_w2 = (const float*)d_in[12];
    const float* rew_b2 = (const float*)d_in[13];
    const float* saf_w1 = (const float*)d_in[14];
    const float* saf_b1 = (const float*)d_in[15];
    const float* saf_w2 = (const float*)d_in[16];
    const float* saf_b2 = (const float*)d_in[17];

    float* out = (float*)d_out;
    float* states = out;
    float* obs = out + (long)BB * (TT + 1) * SS;
    float* rew = obs + (long)BB * TT * OO;
    float* saf = rew + (long)BB * TT;

    cudaFuncSetAttribute(scan_kernel, cudaFuncAttributeMaxDynamicSharedMemorySize,
                         (int)sizeof(ScanSmem));
    cudaFuncSetAttribute(heads_kernel, cudaFuncAttributeMaxDynamicSharedMemorySize,
                         (int)sizeof(HeadSmem));

    scan_kernel<<<BB / 16, 256, sizeof(ScanSmem)>>>(
        initial_state, actions, W_ih, W_hh, b_ih, b_hh, states);
    heads_kernel<<<(BB * TT) / 128, 512, sizeof(HeadSmem)>>>(
        states, dec_w1, dec_b1, dec_w2, dec_b2,
        rew_w1, rew_b1, rew_w2, rew_b2,
        saf_w1, saf_b1, saf_w2, saf_b2,
        obs, rew, saf);
}